// round 14
// baseline (speedup 1.0000x reference)
#include <cuda_runtime.h>
#include <cuda_fp16.h>
#include <math.h>
#include <stdint.h>

#define BB 2
#define TT 4096
#define EE 512
#define HH 8
#define DD 64
#define CHUNK 128
#define NCH (TT/CHUNK)     // 32
#define NBH (BB*HH)        // 16
#define EPSF 1e-6f
#define MROWS (BB*TT)      // 8192
#define WSZ (EE*EE)

// ---------------- scratch (__device__ globals) ---------------------------------
__device__ float g_Mc[NBH*NCH*DD*DD];
__device__ float g_zc[NBH*NCH*DD];
__device__ float g_Mp[NBH*NCH*DD*DD];
__device__ float g_zp[NBH*NCH*DD];

__device__ __half g_xf[MROWS*EE];
__device__ __half g_qf[MROWS*EE];
__device__ __half g_kf[MROWS*EE];
__device__ __half g_vf[MROWS*EE];
__device__ __half g_af[MROWS*EE];
__device__ __half g_wf[4*WSZ];

// ---------------- helpers -------------------------------------------------------
__device__ __forceinline__ uint32_t smem_u32(const void* p) {
    uint32_t a;
    asm("{ .reg .u64 t; cvta.to.shared.u64 t, %1; cvt.u32.u64 %0, t; }"
        : "=r"(a) : "l"(p));
    return a;
}

#define SWZ128(x) ((x) ^ (((x) >> 3) & 0x70))

__device__ __forceinline__ void cp16(uint32_t dst, const void* src) {
    asm volatile("cp.async.cg.shared.global [%0], [%1], 16;" :: "r"(dst), "l"(src));
}
__device__ __forceinline__ void cp_commit() {
    asm volatile("cp.async.commit_group;" ::: "memory");
}
__device__ __forceinline__ void cp_wait0() {
    asm volatile("cp.async.wait_group 0;" ::: "memory");
}

__device__ __forceinline__ void ldsm_x4(uint32_t r[4], uint32_t addr) {
    asm volatile("ldmatrix.sync.aligned.m8n8.x4.shared.b16 {%0,%1,%2,%3}, [%4];"
                 : "=r"(r[0]), "=r"(r[1]), "=r"(r[2]), "=r"(r[3]) : "r"(addr));
}
__device__ __forceinline__ void ldsm_x2(uint32_t r[2], uint32_t addr) {
    asm volatile("ldmatrix.sync.aligned.m8n8.x2.shared.b16 {%0,%1}, [%2];"
                 : "=r"(r[0]), "=r"(r[1]) : "r"(addr));
}
__device__ __forceinline__ void mma_f16(float c[4], const uint32_t a[4], const uint32_t b[2]) {
    asm volatile(
        "mma.sync.aligned.m16n8k16.row.col.f32.f16.f16.f32 "
        "{%0,%1,%2,%3}, {%4,%5,%6,%7}, {%8,%9}, {%0,%1,%2,%3};"
        : "+f"(c[0]), "+f"(c[1]), "+f"(c[2]), "+f"(c[3])
        : "r"(a[0]), "r"(a[1]), "r"(a[2]), "r"(a[3]), "r"(b[0]), "r"(b[1]));
}

// ---------------- convert: fp32 -> fp16 -----------------------------------------
__global__ __launch_bounds__(256) void cvt16_kernel(
    const float* __restrict__ s, __half* __restrict__ d, int n4)
{
    int i = blockIdx.x * 256 + threadIdx.x;
    if (i >= n4) return;
    float4 v = ((const float4*)s)[i];
    __half2* dp = (__half2*)d;
    dp[i*2+0] = __floats2half2_rn(v.x, v.y);
    dp[i*2+1] = __floats2half2_rn(v.z, v.w);
}

__global__ __launch_bounds__(256) void cvtw_kernel(
    const float* __restrict__ w0, const float* __restrict__ w1,
    const float* __restrict__ w2, const float* __restrict__ w3,
    __half* __restrict__ d)
{
    int g = blockIdx.y;
    const float* s = (g == 0) ? w0 : (g == 1) ? w1 : (g == 2) ? w2 : w3;
    int i = blockIdx.x * 256 + threadIdx.x;
    if (i >= WSZ/4) return;
    float4 v = ((const float4*)s)[i];
    __half2* dp = (__half2*)(d + (size_t)g * WSZ);
    dp[i*2+0] = __floats2half2_rn(v.x, v.y);
    dp[i*2+1] = __floats2half2_rn(v.z, v.w);
}

// ---------------- mma.sync fp16 GEMM, cp.async double-buffered ------------------
#define OF_A 0
#define OF_B 16384
#define STAGE_BYTES 32768
#define OF_BIAS (2*STAGE_BYTES)
#define GSM_BYTES (2*STAGE_BYTES + 512 + 256)

template<int F16OUT>
__global__ __launch_bounds__(256, 2) void gemm_f16(
    const __half* __restrict__ Af, const __half* __restrict__ Wf,
    const float* b0, const float* b1, const float* b2,
    void* Y0, void* Y1, void* Y2, int actmask)
{
    extern __shared__ char smem_raw[];
    uint32_t sb0 = smem_u32(smem_raw);
    uint32_t sb  = (sb0 + 127) & ~127u;
    char* smb = smem_raw + (sb - sb0);

    const int tid = threadIdx.x, lid = tid & 31, wid = tid >> 5;
    const int wm = (wid & 1) * 64;
    const int wn = (wid >> 1) * 32;
    const int g  = blockIdx.y >> 2;
    const int m0 = blockIdx.x * 128, n0 = (blockIdx.y & 3) * 128;

    const __half* Bf = Wf + (size_t)g * WSZ;
    const float* bias = (g == 0) ? b0 : (g == 1) ? b1 : b2;
    void* Yv = (g == 0) ? Y0 : (g == 1) ? Y1 : Y2;
    const bool act = (actmask >> g) & 1;

    float* sbias = (float*)(smb + OF_BIAS);
    if (tid < 128) sbias[tid] = bias[n0 + tid];

    float acc[4][4][4];
#pragma unroll
    for (int mi = 0; mi < 4; mi++)
#pragma unroll
        for (int ni = 0; ni < 4; ni++)
#pragma unroll
            for (int kk = 0; kk < 4; kk++) acc[mi][ni][kk] = 0.f;

    const int arow = wm + (lid & 15);
    const int acolb = (lid >> 4) << 3;
    const int brow = wn + (lid & 7);
    const int bcolb = (lid & 8);

    const int lrow = tid >> 3, lj = tid & 7;
#define ISSUE_LOAD(st, k0) do {                                                   \
    uint32_t base = sb + (st) * STAGE_BYTES;                                      \
    _Pragma("unroll")                                                             \
    for (int p = 0; p < 4; p++) {                                                 \
        int row = lrow + p * 32;                                                  \
        uint32_t off = SWZ128((uint32_t)(row * 128 + lj * 16));                   \
        cp16(base + OF_A + off, Af + (size_t)(m0 + row) * EE + (k0) + lj * 8);    \
        cp16(base + OF_B + off, Bf + (size_t)(n0 + row) * EE + (k0) + lj * 8);    \
    }                                                                             \
    cp_commit();                                                                  \
} while (0)

    ISSUE_LOAD(0, 0);
    int cur = 0;
    for (int c = 0; c < 8; c++) {
        cp_wait0();
        __syncthreads();
        if (c < 7) ISSUE_LOAD(cur ^ 1, (c + 1) * 64);

        uint32_t tb = sb + cur * STAGE_BYTES;
#pragma unroll
        for (int ks = 0; ks < 4; ks++) {
            uint32_t ar[4][4], br[4][2];
            int ak = ks * 16 + acolb;
#pragma unroll
            for (int mi = 0; mi < 4; mi++) {
                uint32_t off = SWZ128((uint32_t)((arow + mi * 16) * 128 + ak * 2));
                ldsm_x4(ar[mi], tb + OF_A + off);
            }
            int bk = ks * 16 + bcolb;
#pragma unroll
            for (int ni = 0; ni < 4; ni++) {
                uint32_t off = SWZ128((uint32_t)((brow + ni * 8) * 128 + bk * 2));
                ldsm_x2(br[ni], tb + OF_B + off);
            }
#pragma unroll
            for (int mi = 0; mi < 4; mi++)
#pragma unroll
                for (int ni = 0; ni < 4; ni++)
                    mma_f16(acc[mi][ni], ar[mi], br[ni]);
        }
        cur ^= 1;
    }
#undef ISSUE_LOAD

    const int er = lid >> 2, ec = (lid & 3) * 2;
#pragma unroll
    for (int mi = 0; mi < 4; mi++) {
#pragma unroll
        for (int ni = 0; ni < 4; ni++) {
            int nn = wn + ni * 8 + ec;
            float bb0 = sbias[nn], bb1 = sbias[nn + 1];
            int m1 = m0 + wm + mi * 16 + er;
            float2 v0 = make_float2(acc[mi][ni][0] + bb0, acc[mi][ni][1] + bb1);
            float2 v1 = make_float2(acc[mi][ni][2] + bb0, acc[mi][ni][3] + bb1);
            if (act) {
                v0.x = (v0.x > 0.f) ? (v0.x + 1.f) : expf(v0.x);
                v0.y = (v0.y > 0.f) ? (v0.y + 1.f) : expf(v0.y);
                v1.x = (v1.x > 0.f) ? (v1.x + 1.f) : expf(v1.x);
                v1.y = (v1.y > 0.f) ? (v1.y + 1.f) : expf(v1.y);
            }
            if (F16OUT) {
                __half* Y = (__half*)Yv;
                *(__half2*)&Y[(size_t)m1 * EE + n0 + nn]       = __floats2half2_rn(v0.x, v0.y);
                *(__half2*)&Y[(size_t)(m1 + 8) * EE + n0 + nn] = __floats2half2_rn(v1.x, v1.y);
            } else {
                float* Y = (float*)Yv;
                *(float2*)&Y[(size_t)m1 * EE + n0 + nn] = v0;
                *(float2*)&Y[(size_t)(m1 + 8) * EE + n0 + nn] = v1;
            }
        }
    }
}

// ---------------- Pass A: Mc = K^T V + z via mma --------------------------------
// smem halves: KT [64][136] @0, VT [64][136] @8704. 34816 B total.
__global__ __launch_bounds__(256) void chunk_sums_kernel()
{
    int blk = blockIdx.x;
    int bh = blk / NCH, c = blk % NCH;
    int b = bh / HH, h = bh % HH;

    extern __shared__ __half sh[];
    __half* KT = sh;
    __half* VT = sh + 64 * 136;
    int tid = threadIdx.x;
    size_t base = ((size_t)b * TT + (size_t)c * CHUNK) * EE + h * DD;

    // coalesced global loads (lanes vary e2); 4-way STS conflict is acceptable
    for (int i = tid; i < 128 * 32; i += 256) {
        int e2 = i & 31, t = i >> 5;
        __half2 kv = *(const __half2*)&g_kf[base + (size_t)t * EE + e2 * 2];
        __half2 vv = *(const __half2*)&g_vf[base + (size_t)t * EE + e2 * 2];
        KT[(2*e2) * 136 + t] = __low2half(kv);  KT[(2*e2+1) * 136 + t] = __high2half(kv);
        VT[(2*e2) * 136 + t] = __low2half(vv);  VT[(2*e2+1) * 136 + t] = __high2half(vv);
    }
    __syncthreads();

    uint32_t sb = smem_u32(sh);
    int lid = tid & 31, wid = tid >> 5;
    int wm = (wid & 1) * 32, wn = (wid >> 1) * 16;
    float acc[2][2][4];
#pragma unroll
    for (int mi = 0; mi < 2; mi++)
#pragma unroll
        for (int ni = 0; ni < 2; ni++)
#pragma unroll
            for (int kk = 0; kk < 4; kk++) acc[mi][ni][kk] = 0.f;

    const int arow = lid & 15, acol = (lid >> 4) << 3;
    const int brow = lid & 7,  bcol = lid & 8;

#pragma unroll
    for (int kt = 0; kt < 8; kt++) {
        int k0 = kt * 16;
        uint32_t ar[2][4], br[2][2];
#pragma unroll
        for (int mi = 0; mi < 2; mi++)
            ldsm_x4(ar[mi], sb + ((wm + mi*16 + arow) * 136 + k0 + acol) * 2);
#pragma unroll
        for (int ni = 0; ni < 2; ni++)
            ldsm_x2(br[ni], sb + (64*136 + (wn + ni*8 + brow) * 136 + k0 + bcol) * 2);
#pragma unroll
        for (int mi = 0; mi < 2; mi++)
#pragma unroll
            for (int ni = 0; ni < 2; ni++)
                mma_f16(acc[mi][ni], ar[mi], br[ni]);
    }

    int er = lid >> 2, ec = (lid & 3) * 2;
    float* Mout = g_Mc + (size_t)blk * DD * DD;
#pragma unroll
    for (int mi = 0; mi < 2; mi++)
#pragma unroll
        for (int ni = 0; ni < 2; ni++) {
            int d = wm + mi * 16 + er, e = wn + ni * 8 + ec;
            *(float2*)&Mout[d * DD + e]       = make_float2(acc[mi][ni][0], acc[mi][ni][1]);
            *(float2*)&Mout[(d + 8) * DD + e] = make_float2(acc[mi][ni][2], acc[mi][ni][3]);
        }

    if (tid < DD) {
        float zz = 0.f;
        const __half2* row = (const __half2*)&KT[tid * 136];
#pragma unroll 8
        for (int t2 = 0; t2 < 64; t2++) {
            float2 f = __half22float2(row[t2]);
            zz += f.x + f.y;
        }
        g_zc[(size_t)blk * DD + tid] = zz;
    }
}

// ---------------- Pass B: exclusive prefix (MLP-overlapped loads) ---------------
__global__ void prefix_kernel()
{
    int idx = blockIdx.x * 256 + threadIdx.x;
    const int PER = DD * DD + DD;
    if (idx >= NBH * PER) return;
    int bh = idx / PER;
    int r  = idx % PER;
    if (r < DD * DD) {
        float vals[NCH];
#pragma unroll
        for (int c = 0; c < NCH; c++)
            vals[c] = g_Mc[(size_t)(bh * NCH + c) * DD * DD + r];
        float run = 0.f;
#pragma unroll
        for (int c = 0; c < NCH; c++) {
            g_Mp[(size_t)(bh * NCH + c) * DD * DD + r] = run;
            run += vals[c];
        }
    } else {
        int d = r - DD * DD;
        float vals[NCH];
#pragma unroll
        for (int c = 0; c < NCH; c++)
            vals[c] = g_zc[(size_t)(bh * NCH + c) * DD + d];
        float run = 0.f;
#pragma unroll
        for (int c = 0; c < NCH; c++) {
            g_zp[(size_t)(bh * NCH + c) * DD + d] = run;
            run += vals[c];
        }
    }
}

// ---------------- Pass C: tensorized intra-chunk attention ----------------------
#define CA_QF 0
#define CA_KF 9216
#define CA_VT 18432
#define CA_STH 27136
#define CA_STL 31744
#define CA_A  36352
#define CA_ZB 107520
#define CA_DIB 107776
#define CA_BYTES 108544

__global__ __launch_bounds__(256, 1) void chunk_attn_kernel()
{
    int blk = blockIdx.x;
    int bh = blk / NCH, c = blk % NCH;
    int b = bh / HH, h = bh % HH;

    extern __shared__ char smc[];
    __half* sh = (__half*)smc;
    float* zf  = (float*)(smc + CA_ZB);
    float* sdi = (float*)(smc + CA_DIB);
    uint32_t sb = smem_u32(smc);

    int tid = threadIdx.x, lid = tid & 31, wid = tid >> 5;
    size_t base = ((size_t)b * TT + (size_t)c * CHUNK) * EE + h * DD;
    const float* Mp = g_Mp + (size_t)blk * DD * DD;
    const float* zp = g_zp + (size_t)blk * DD;

    // q,k row-major fp16
    for (int i = tid; i < 128 * 8; i += 256) {
        int row = i >> 3, j = i & 7;
        *(uint4*)&sh[CA_QF + row * 72 + j * 8] =
            *(const uint4*)&g_qf[base + (size_t)row * EE + j * 8];
        *(uint4*)&sh[CA_KF + row * 72 + j * 8] =
            *(const uint4*)&g_kf[base + (size_t)row * EE + j * 8];
    }
    // V transposed (coalesced loads, conflicted stores — measured faster)
    for (int i = tid; i < 128 * 32; i += 256) {
        int e2 = i & 31, t = i >> 5;
        __half2 vv = *(const __half2*)&g_vf[base + (size_t)t * EE + e2 * 2];
        sh[CA_VT + (2*e2) * 136 + t] = __low2half(vv);
        sh[CA_VT + (2*e2+1) * 136 + t] = __high2half(vv);
    }
    // S^T hi/lo
    for (int i = tid; i < 64 * 16; i += 256) {
        int d = i >> 4, e4 = (i & 15) * 4;
        float4 s4 = *(const float4*)&Mp[d * DD + e4];
        float fs[4] = {s4.x, s4.y, s4.z, s4.w};
#pragma unroll
        for (int j = 0; j < 4; j++) {
            __half hi = __float2half(fs[j]);
            sh[CA_STH + (e4 + j) * 72 + d] = hi;
            sh[CA_STL + (e4 + j) * 72 + d] = __float2half(fs[j] - __half2float(hi));
        }
    }
    if (tid < DD) zf[tid] = zp[tid];
    __syncthreads();

    // ---- phase 1: A = Q K^T (causal-masked), fp16 into smem ----
    {
        int wm = (wid & 1) * 64, wn = (wid >> 1) * 32;
        const int arow = lid & 15, acol = (lid >> 4) << 3;
        const int brow = lid & 7,  bcol = lid & 8;
        float acc[4][4][4];
#pragma unroll
        for (int mi = 0; mi < 4; mi++)
#pragma unroll
            for (int ni = 0; ni < 4; ni++)
#pragma unroll
                for (int kk = 0; kk < 4; kk++) acc[mi][ni][kk] = 0.f;

#pragma unroll
        for (int kt = 0; kt < 4; kt++) {
            int k0 = kt * 16;
            uint32_t ar[4][4], br[4][2];
#pragma unroll
            for (int mi = 0; mi < 4; mi++)
                ldsm_x4(ar[mi], sb + (CA_QF + (wm + mi*16 + arow) * 72 + k0 + acol) * 2);
#pragma unroll
            for (int ni = 0; ni < 4; ni++)
                ldsm_x2(br[ni], sb + (CA_KF + (wn + ni*8 + brow) * 72 + k0 + bcol) * 2);
#pragma unroll
            for (int mi = 0; mi < 4; mi++)
#pragma unroll
                for (int ni = 0; ni < 4; ni++)
                    mma_f16(acc[mi][ni], ar[mi], br[ni]);
        }

        int er = lid >> 2, ec = (lid & 3) * 2;
#pragma unroll
        for (int mi = 0; mi < 4; mi++)
#pragma unroll
            for (int ni = 0; ni < 4; ni++) {
                int t = wm + mi * 16 + er, s = wn + ni * 8 + ec;
                float c0 = (s     <= t) ? acc[mi][ni][0] : 0.f;
                float c1 = (s + 1 <= t) ? acc[mi][ni][1] : 0.f;
                int t2 = t + 8;
                float c2 = (s     <= t2) ? acc[mi][ni][2] : 0.f;
                float c3 = (s + 1 <= t2) ? acc[mi][ni][3] : 0.f;
                *(__half2*)&sh[CA_A + t  * 136 + s] = __floats2half2_rn(c0, c1);
                *(__half2*)&sh[CA_A + t2 * 136 + s] = __floats2half2_rn(c2, c3);
            }
    }
    __syncthreads();

    // ---- denominators ----
    if (tid < CHUNK) {
        int t = tid;
        float den = EPSF;
        const __half2* qr = (const __half2*)&sh[CA_QF + t * 72];
#pragma unroll 8
        for (int d2 = 0; d2 < 32; d2++) {
            float2 q = __half22float2(qr[d2]);
            den += q.x * zf[2*d2] + q.y * zf[2*d2 + 1];
        }
        const __half2* ar = (const __half2*)&sh[CA_A + t * 136];
#pragma unroll 8
        for (int s2 = 0; s2 < 64; s2++) {
            float2 a = __half22float2(ar[s2]);
            den += a.x + a.y;
        }
        sdi[t] = 1.f / den;
    }
    __syncthreads();

    // ---- phase 2: out = (A V + Q Sh + Q Sl) * inv_den -> g_af fp16 ----
    {
        int wm = (wid & 1) * 64, wn = (wid >> 1) * 16;
        const int arow = lid & 15, acol = (lid >> 4) << 3;
        const int brow = lid & 7,  bcol = lid & 8;
        float acc[4][2][4];
#pragma unroll
        for (int mi = 0; mi < 4; mi++)
#pragma unroll
            for (int ni = 0; ni < 2; ni++)
#pragma unroll
                for (int kk = 0; kk < 4; kk++) acc[mi][ni][kk] = 0.f;

        // A V  (k = s, 8 tiles)
#pragma unroll
        for (int kt = 0; kt < 8; kt++) {
            int k0 = kt * 16;
            uint32_t ar[4][4], br[2][2];
#pragma unroll
            for (int mi = 0; mi < 4; mi++)
                ldsm_x4(ar[mi], sb + (CA_A + (wm + mi*16 + arow) * 136 + k0 + acol) * 2);
#pragma unroll
            for (int ni = 0; ni < 2; ni++)
                ldsm_x2(br[ni], sb + (CA_VT + (wn + ni*8 + brow) * 136 + k0 + bcol) * 2);
#pragma unroll
            for (int mi = 0; mi < 4; mi++)
#pragma unroll
                for (int ni = 0; ni < 2; ni++)
                    mma_f16(acc[mi][ni], ar[mi], br[ni]);
        }
        // Q S_hi + Q S_lo  (k = d, 4 tiles each)
#pragma unroll
        for (int pass = 0; pass < 2; pass++) {
            int stoff = pass ? CA_STL : CA_STH;
#pragma unroll
            for (int kt = 0; kt < 4; kt++) {
                int k0 = kt * 16;
                uint32_t ar[4][4], br[2][2];
#pragma unroll
                for (int mi = 0; mi < 4; mi++)
                    ldsm_x4(ar[mi], sb + (CA_QF + (wm + mi*16 + arow) * 72 + k0 + acol) * 2);
#pragma unroll
                for (int ni = 0; ni < 2; ni++)
                    ldsm_x2(br[ni], sb + (stoff + (wn + ni*8 + brow) * 72 + k0 + bcol) * 2);
#pragma unroll
                for (int mi = 0; mi < 4; mi++)
#pragma unroll
                    for (int ni = 0; ni < 2; ni++)
                        mma_f16(acc[mi][ni], ar[mi], br[ni]);
            }
        }

        int er = lid >> 2, ec = (lid & 3) * 2;
#pragma unroll
        for (int mi = 0; mi < 4; mi++)
#pragma unroll
            for (int ni = 0; ni < 2; ni++) {
                int t = wm + mi * 16 + er, e = wn + ni * 8 + ec;
                float i0 = sdi[t], i1 = sdi[t + 8];
                *(__half2*)&g_af[base + (size_t)t * EE + e] =
                    __floats2half2_rn(acc[mi][ni][0] * i0, acc[mi][ni][1] * i0);
                *(__half2*)&g_af[base + (size_t)(t + 8) * EE + e] =
                    __floats2half2_rn(acc[mi][ni][2] * i1, acc[mi][ni][3] * i1);
            }
    }
}

// ---------------- host ----------------------------------------------------------
extern "C" void kernel_launch(void* const* d_in, const int* in_sizes, int n_in,
                              void* d_out, int out_size)
{
    const float* x  = (const float*)d_in[0];
    const float* Wq = (const float*)d_in[1];
    const float* bq = (const float*)d_in[2];
    const float* Wk = (const float*)d_in[3];
    const float* bk = (const float*)d_in[4];
    const float* Wv = (const float*)d_in[5];
    const float* bv = (const float*)d_in[6];
    const float* Wo = (const float*)d_in[7];
    const float* bo = (const float*)d_in[8];
    float* out = (float*)d_out;

    __half *xf, *qf, *kf, *vf, *af, *wf;
    cudaGetSymbolAddress((void**)&xf, g_xf);
    cudaGetSymbolAddress((void**)&qf, g_qf);
    cudaGetSymbolAddress((void**)&kf, g_kf);
    cudaGetSymbolAddress((void**)&vf, g_vf);
    cudaGetSymbolAddress((void**)&af, g_af);
    cudaGetSymbolAddress((void**)&wf, g_wf);

    cudaFuncSetAttribute(gemm_f16<0>, cudaFuncAttributeMaxDynamicSharedMemorySize, GSM_BYTES);
    cudaFuncSetAttribute(gemm_f16<1>, cudaFuncAttributeMaxDynamicSharedMemorySize, GSM_BYTES);
    cudaFuncSetAttribute(chunk_sums_kernel,
                         cudaFuncAttributeMaxDynamicSharedMemorySize, 2 * 64 * 136 * 2);
    cudaFuncSetAttribute(chunk_attn_kernel,
                         cudaFuncAttributeMaxDynamicSharedMemorySize, CA_BYTES);

    cvt16_kernel<<<(MROWS*EE/4 + 255)/256, 256>>>(x, xf, MROWS*EE/4);
    dim3 wg((WSZ/4 + 255)/256, 4);
    cvtw_kernel<<<wg, 256>>>(Wq, Wk, Wv, Wo, wf);

    // fused QKV projection -> fp16 q/k/v with elu+1 on q,k
    dim3 gq(MROWS / 128, 12);
    gemm_f16<1><<<gq, 256, GSM_BYTES>>>(xf, wf, bq, bk, bv, qf, kf, vf, 0x3);

    chunk_sums_kernel<<<NBH * NCH, 256, 2 * 64 * 136 * 2>>>();

    int totalPref = NBH * (DD * DD + DD);
    prefix_kernel<<<(totalPref + 255) / 256, 256>>>();

    chunk_attn_kernel<<<NBH * NCH, 256, CA_BYTES>>>();

    // output projection -> fp32 d_out
    dim3 go(MROWS / 128, 4);
    gemm_f16<0><<<go, 256, GSM_BYTES>>>(af, wf + 3*WSZ, bo, bo, bo, out, out, out, 0x0);
}

// round 15
// speedup vs baseline: 1.0136x; 1.0136x over previous
#include <cuda_runtime.h>
#include <cuda_fp16.h>
#include <math.h>
#include <stdint.h>

#define BB 2
#define TT 4096
#define EE 512
#define HH 8
#define DD 64
#define CHUNK 128
#define NCH (TT/CHUNK)     // 32
#define NBH (BB*HH)        // 16
#define EPSF 1e-6f
#define MROWS (BB*TT)      // 8192
#define WSZ (EE*EE)

// ---------------- scratch (__device__ globals) ---------------------------------
__device__ float g_Mc[NBH*NCH*DD*DD];
__device__ float g_zc[NBH*NCH*DD];
__device__ float g_Mp[NBH*NCH*DD*DD];
__device__ float g_zp[NBH*NCH*DD];

__device__ __half g_xf[MROWS*EE];
__device__ __half g_qf[MROWS*EE];
__device__ __half g_kf[MROWS*EE];
__device__ __half g_vf[MROWS*EE];
__device__ __half g_af[MROWS*EE];
__device__ __half g_wf[4*WSZ];

// ---------------- helpers -------------------------------------------------------
__device__ __forceinline__ uint32_t smem_u32(const void* p) {
    uint32_t a;
    asm("{ .reg .u64 t; cvta.to.shared.u64 t, %1; cvt.u32.u64 %0, t; }"
        : "=r"(a) : "l"(p));
    return a;
}

#define SWZ128(x) ((x) ^ (((x) >> 3) & 0x70))

__device__ __forceinline__ void cp16(uint32_t dst, const void* src) {
    asm volatile("cp.async.cg.shared.global [%0], [%1], 16;" :: "r"(dst), "l"(src));
}
__device__ __forceinline__ void cp_commit() {
    asm volatile("cp.async.commit_group;" ::: "memory");
}
__device__ __forceinline__ void cp_wait0() {
    asm volatile("cp.async.wait_group 0;" ::: "memory");
}

__device__ __forceinline__ void ldsm_x4(uint32_t r[4], uint32_t addr) {
    asm volatile("ldmatrix.sync.aligned.m8n8.x4.shared.b16 {%0,%1,%2,%3}, [%4];"
                 : "=r"(r[0]), "=r"(r[1]), "=r"(r[2]), "=r"(r[3]) : "r"(addr));
}
__device__ __forceinline__ void ldsm_x2(uint32_t r[2], uint32_t addr) {
    asm volatile("ldmatrix.sync.aligned.m8n8.x2.shared.b16 {%0,%1}, [%2];"
                 : "=r"(r[0]), "=r"(r[1]) : "r"(addr));
}
__device__ __forceinline__ void mma_f16(float c[4], const uint32_t a[4], const uint32_t b[2]) {
    asm volatile(
        "mma.sync.aligned.m16n8k16.row.col.f32.f16.f16.f32 "
        "{%0,%1,%2,%3}, {%4,%5,%6,%7}, {%8,%9}, {%0,%1,%2,%3};"
        : "+f"(c[0]), "+f"(c[1]), "+f"(c[2]), "+f"(c[3])
        : "r"(a[0]), "r"(a[1]), "r"(a[2]), "r"(a[3]), "r"(b[0]), "r"(b[1]));
}

// ---------------- convert: fp32 -> fp16 (x + 4 weights, one launch) -------------
#define XN4 (MROWS*EE/4)      // 1048576
#define WN4 (WSZ/4)           // 65536
__global__ __launch_bounds__(256) void cvt_all_kernel(
    const float* __restrict__ x,
    const float* __restrict__ w0, const float* __restrict__ w1,
    const float* __restrict__ w2, const float* __restrict__ w3,
    __half* __restrict__ xf, __half* __restrict__ wf)
{
    int i = blockIdx.x * 256 + threadIdx.x;
    const float* s;
    __half2* dp;
    int j;
    if (i < XN4) {
        s = x; dp = (__half2*)xf; j = i;
    } else {
        int k = i - XN4;
        int g = k / WN4;
        j = k - g * WN4;
        s = (g == 0) ? w0 : (g == 1) ? w1 : (g == 2) ? w2 : w3;
        dp = (__half2*)(wf + (size_t)g * WSZ);
    }
    float4 v = ((const float4*)s)[j];
    dp[j*2+0] = __floats2half2_rn(v.x, v.y);
    dp[j*2+1] = __floats2half2_rn(v.z, v.w);
}

// ---------------- mma.sync fp16 GEMM, cp.async double-buffered ------------------
#define OF_A 0
#define OF_B 16384
#define STAGE_BYTES 32768
#define OF_BIAS (2*STAGE_BYTES)
#define GSM_BYTES (2*STAGE_BYTES + 512 + 256)

template<int F16OUT>
__global__ __launch_bounds__(256, 2) void gemm_f16(
    const __half* __restrict__ Af, const __half* __restrict__ Wf,
    const float* b0, const float* b1, const float* b2,
    void* Y0, void* Y1, void* Y2, int actmask)
{
    extern __shared__ char smem_raw[];
    uint32_t sb0 = smem_u32(smem_raw);
    uint32_t sb  = (sb0 + 127) & ~127u;
    char* smb = smem_raw + (sb - sb0);

    const int tid = threadIdx.x, lid = tid & 31, wid = tid >> 5;
    const int wm = (wid & 1) * 64;
    const int wn = (wid >> 1) * 32;
    const int g  = blockIdx.y >> 2;
    const int m0 = blockIdx.x * 128, n0 = (blockIdx.y & 3) * 128;

    const __half* Bf = Wf + (size_t)g * WSZ;
    const float* bias = (g == 0) ? b0 : (g == 1) ? b1 : b2;
    void* Yv = (g == 0) ? Y0 : (g == 1) ? Y1 : Y2;
    const bool act = (actmask >> g) & 1;

    float* sbias = (float*)(smb + OF_BIAS);
    if (tid < 128) sbias[tid] = bias[n0 + tid];

    float acc[4][4][4];
#pragma unroll
    for (int mi = 0; mi < 4; mi++)
#pragma unroll
        for (int ni = 0; ni < 4; ni++)
#pragma unroll
            for (int kk = 0; kk < 4; kk++) acc[mi][ni][kk] = 0.f;

    const int arow = wm + (lid & 15);
    const int acolb = (lid >> 4) << 3;
    const int brow = wn + (lid & 7);
    const int bcolb = (lid & 8);

    const int lrow = tid >> 3, lj = tid & 7;
#define ISSUE_LOAD(st, k0) do {                                                   \
    uint32_t base = sb + (st) * STAGE_BYTES;                                      \
    _Pragma("unroll")                                                             \
    for (int p = 0; p < 4; p++) {                                                 \
        int row = lrow + p * 32;                                                  \
        uint32_t off = SWZ128((uint32_t)(row * 128 + lj * 16));                   \
        cp16(base + OF_A + off, Af + (size_t)(m0 + row) * EE + (k0) + lj * 8);    \
        cp16(base + OF_B + off, Bf + (size_t)(n0 + row) * EE + (k0) + lj * 8);    \
    }                                                                             \
    cp_commit();                                                                  \
} while (0)

    ISSUE_LOAD(0, 0);
    int cur = 0;
    for (int c = 0; c < 8; c++) {
        cp_wait0();
        __syncthreads();
        if (c < 7) ISSUE_LOAD(cur ^ 1, (c + 1) * 64);

        uint32_t tb = sb + cur * STAGE_BYTES;
#pragma unroll
        for (int ks = 0; ks < 4; ks++) {
            uint32_t ar[4][4], br[4][2];
            int ak = ks * 16 + acolb;
#pragma unroll
            for (int mi = 0; mi < 4; mi++) {
                uint32_t off = SWZ128((uint32_t)((arow + mi * 16) * 128 + ak * 2));
                ldsm_x4(ar[mi], tb + OF_A + off);
            }
            int bk = ks * 16 + bcolb;
#pragma unroll
            for (int ni = 0; ni < 4; ni++) {
                uint32_t off = SWZ128((uint32_t)((brow + ni * 8) * 128 + bk * 2));
                ldsm_x2(br[ni], tb + OF_B + off);
            }
#pragma unroll
            for (int mi = 0; mi < 4; mi++)
#pragma unroll
                for (int ni = 0; ni < 4; ni++)
                    mma_f16(acc[mi][ni], ar[mi], br[ni]);
        }
        cur ^= 1;
    }
#undef ISSUE_LOAD

    const int er = lid >> 2, ec = (lid & 3) * 2;
#pragma unroll
    for (int mi = 0; mi < 4; mi++) {
#pragma unroll
        for (int ni = 0; ni < 4; ni++) {
            int nn = wn + ni * 8 + ec;
            float bb0 = sbias[nn], bb1 = sbias[nn + 1];
            int m1 = m0 + wm + mi * 16 + er;
            float2 v0 = make_float2(acc[mi][ni][0] + bb0, acc[mi][ni][1] + bb1);
            float2 v1 = make_float2(acc[mi][ni][2] + bb0, acc[mi][ni][3] + bb1);
            if (act) {
                v0.x = (v0.x > 0.f) ? (v0.x + 1.f) : expf(v0.x);
                v0.y = (v0.y > 0.f) ? (v0.y + 1.f) : expf(v0.y);
                v1.x = (v1.x > 0.f) ? (v1.x + 1.f) : expf(v1.x);
                v1.y = (v1.y > 0.f) ? (v1.y + 1.f) : expf(v1.y);
            }
            if (F16OUT) {
                __half* Y = (__half*)Yv;
                *(__half2*)&Y[(size_t)m1 * EE + n0 + nn]       = __floats2half2_rn(v0.x, v0.y);
                *(__half2*)&Y[(size_t)(m1 + 8) * EE + n0 + nn] = __floats2half2_rn(v1.x, v1.y);
            } else {
                float* Y = (float*)Yv;
                *(float2*)&Y[(size_t)m1 * EE + n0 + nn] = v0;
                *(float2*)&Y[(size_t)(m1 + 8) * EE + n0 + nn] = v1;
            }
        }
    }
}

// ---------------- Pass A: Mc = K^T V + z via mma --------------------------------
__global__ __launch_bounds__(256) void chunk_sums_kernel()
{
    int blk = blockIdx.x;
    int bh = blk / NCH, c = blk % NCH;
    int b = bh / HH, h = bh % HH;

    extern __shared__ __half sh[];
    __half* KT = sh;
    __half* VT = sh + 64 * 136;
    int tid = threadIdx.x;
    size_t base = ((size_t)b * TT + (size_t)c * CHUNK) * EE + h * DD;

    for (int i = tid; i < 128 * 32; i += 256) {
        int e2 = i & 31, t = i >> 5;
        __half2 kv = *(const __half2*)&g_kf[base + (size_t)t * EE + e2 * 2];
        __half2 vv = *(const __half2*)&g_vf[base + (size_t)t * EE + e2 * 2];
        KT[(2*e2) * 136 + t] = __low2half(kv);  KT[(2*e2+1) * 136 + t] = __high2half(kv);
        VT[(2*e2) * 136 + t] = __low2half(vv);  VT[(2*e2+1) * 136 + t] = __high2half(vv);
    }
    __syncthreads();

    uint32_t sb = smem_u32(sh);
    int lid = tid & 31, wid = tid >> 5;
    int wm = (wid & 1) * 32, wn = (wid >> 1) * 16;
    float acc[2][2][4];
#pragma unroll
    for (int mi = 0; mi < 2; mi++)
#pragma unroll
        for (int ni = 0; ni < 2; ni++)
#pragma unroll
            for (int kk = 0; kk < 4; kk++) acc[mi][ni][kk] = 0.f;

    const int arow = lid & 15, acol = (lid >> 4) << 3;
    const int brow = lid & 7,  bcol = lid & 8;

#pragma unroll
    for (int kt = 0; kt < 8; kt++) {
        int k0 = kt * 16;
        uint32_t ar[2][4], br[2][2];
#pragma unroll
        for (int mi = 0; mi < 2; mi++)
            ldsm_x4(ar[mi], sb + ((wm + mi*16 + arow) * 136 + k0 + acol) * 2);
#pragma unroll
        for (int ni = 0; ni < 2; ni++)
            ldsm_x2(br[ni], sb + (64*136 + (wn + ni*8 + brow) * 136 + k0 + bcol) * 2);
#pragma unroll
        for (int mi = 0; mi < 2; mi++)
#pragma unroll
            for (int ni = 0; ni < 2; ni++)
                mma_f16(acc[mi][ni], ar[mi], br[ni]);
    }

    int er = lid >> 2, ec = (lid & 3) * 2;
    float* Mout = g_Mc + (size_t)blk * DD * DD;
#pragma unroll
    for (int mi = 0; mi < 2; mi++)
#pragma unroll
        for (int ni = 0; ni < 2; ni++) {
            int d = wm + mi * 16 + er, e = wn + ni * 8 + ec;
            *(float2*)&Mout[d * DD + e]       = make_float2(acc[mi][ni][0], acc[mi][ni][1]);
            *(float2*)&Mout[(d + 8) * DD + e] = make_float2(acc[mi][ni][2], acc[mi][ni][3]);
        }

    if (tid < DD) {
        float zz = 0.f;
        const __half2* row = (const __half2*)&KT[tid * 136];
#pragma unroll 8
        for (int t2 = 0; t2 < 64; t2++) {
            float2 f = __half22float2(row[t2]);
            zz += f.x + f.y;
        }
        g_zc[(size_t)blk * DD + tid] = zz;
    }
}

// ---------------- Pass B: exclusive prefix (MLP-overlapped loads) ---------------
__global__ void prefix_kernel()
{
    int idx = blockIdx.x * 256 + threadIdx.x;
    const int PER = DD * DD + DD;
    if (idx >= NBH * PER) return;
    int bh = idx / PER;
    int r  = idx % PER;
    if (r < DD * DD) {
        float vals[NCH];
#pragma unroll
        for (int c = 0; c < NCH; c++)
            vals[c] = g_Mc[(size_t)(bh * NCH + c) * DD * DD + r];
        float run = 0.f;
#pragma unroll
        for (int c = 0; c < NCH; c++) {
            g_Mp[(size_t)(bh * NCH + c) * DD * DD + r] = run;
            run += vals[c];
        }
    } else {
        int d = r - DD * DD;
        float vals[NCH];
#pragma unroll
        for (int c = 0; c < NCH; c++)
            vals[c] = g_zc[(size_t)(bh * NCH + c) * DD + d];
        float run = 0.f;
#pragma unroll
        for (int c = 0; c < NCH; c++) {
            g_zp[(size_t)(bh * NCH + c) * DD + d] = run;
            run += vals[c];
        }
    }
}

// ---------------- Pass C: tensorized intra-chunk attention ----------------------
#define CA_QF 0
#define CA_KF 9216
#define CA_VT 18432
#define CA_STH 27136
#define CA_STL 31744
#define CA_A  36352
#define CA_ZB 107520
#define CA_DIB 107776
#define CA_BYTES 108544

__global__ __launch_bounds__(256, 1) void chunk_attn_kernel()
{
    int blk = blockIdx.x;
    int bh = blk / NCH, c = blk % NCH;
    int b = bh / HH, h = bh % HH;

    extern __shared__ char smc[];
    __half* sh = (__half*)smc;
    float* zf  = (float*)(smc + CA_ZB);
    float* sdi = (float*)(smc + CA_DIB);
    uint32_t sb = smem_u32(smc);

    int tid = threadIdx.x, lid = tid & 31, wid = tid >> 5;
    size_t base = ((size_t)b * TT + (size_t)c * CHUNK) * EE + h * DD;
    const float* Mp = g_Mp + (size_t)blk * DD * DD;
    const float* zp = g_zp + (size_t)blk * DD;

    // q,k row-major fp16
    for (int i = tid; i < 128 * 8; i += 256) {
        int row = i >> 3, j = i & 7;
        *(uint4*)&sh[CA_QF + row * 72 + j * 8] =
            *(const uint4*)&g_qf[base + (size_t)row * EE + j * 8];
        *(uint4*)&sh[CA_KF + row * 72 + j * 8] =
            *(const uint4*)&g_kf[base + (size_t)row * EE + j * 8];
    }
    // V transposed (coalesced loads, conflicted stores — measured faster)
    for (int i = tid; i < 128 * 32; i += 256) {
        int e2 = i & 31, t = i >> 5;
        __half2 vv = *(const __half2*)&g_vf[base + (size_t)t * EE + e2 * 2];
        sh[CA_VT + (2*e2) * 136 + t] = __low2half(vv);
        sh[CA_VT + (2*e2+1) * 136 + t] = __high2half(vv);
    }
    // S^T hi/lo
    for (int i = tid; i < 64 * 16; i += 256) {
        int d = i >> 4, e4 = (i & 15) * 4;
        float4 s4 = *(const float4*)&Mp[d * DD + e4];
        float fs[4] = {s4.x, s4.y, s4.z, s4.w};
#pragma unroll
        for (int j = 0; j < 4; j++) {
            __half hi = __float2half(fs[j]);
            sh[CA_STH + (e4 + j) * 72 + d] = hi;
            sh[CA_STL + (e4 + j) * 72 + d] = __float2half(fs[j] - __half2float(hi));
        }
    }
    if (tid < DD) zf[tid] = zp[tid];
    __syncthreads();

    // ---- phase 1: A = Q K^T (causal-masked), fp16 into smem ----
    {
        int wm = (wid & 1) * 64, wn = (wid >> 1) * 32;
        const int arow = lid & 15, acol = (lid >> 4) << 3;
        const int brow = lid & 7,  bcol = lid & 8;
        float acc[4][4][4];
#pragma unroll
        for (int mi = 0; mi < 4; mi++)
#pragma unroll
            for (int ni = 0; ni < 4; ni++)
#pragma unroll
                for (int kk = 0; kk < 4; kk++) acc[mi][ni][kk] = 0.f;

        // skip warps whose whole 64x32 tile is above the diagonal (A==0 there)
        if (wn <= wm + 63) {
#pragma unroll
            for (int kt = 0; kt < 4; kt++) {
                int k0 = kt * 16;
                uint32_t ar[4][4], br[4][2];
#pragma unroll
                for (int mi = 0; mi < 4; mi++)
                    ldsm_x4(ar[mi], sb + (CA_QF + (wm + mi*16 + arow) * 72 + k0 + acol) * 2);
#pragma unroll
                for (int ni = 0; ni < 4; ni++)
                    ldsm_x2(br[ni], sb + (CA_KF + (wn + ni*8 + brow) * 72 + k0 + bcol) * 2);
#pragma unroll
                for (int mi = 0; mi < 4; mi++)
#pragma unroll
                    for (int ni = 0; ni < 4; ni++)
                        if (wn + ni * 8 <= wm + mi * 16 + 15)   // subtile touches diag
                            mma_f16(acc[mi][ni], ar[mi], br[ni]);
            }
        }

        int er = lid >> 2, ec = (lid & 3) * 2;
#pragma unroll
        for (int mi = 0; mi < 4; mi++)
#pragma unroll
            for (int ni = 0; ni < 4; ni++) {
                int t = wm + mi * 16 + er, s = wn + ni * 8 + ec;
                float c0 = (s     <= t) ? acc[mi][ni][0] : 0.f;
                float c1 = (s + 1 <= t) ? acc[mi][ni][1] : 0.f;
                int t2 = t + 8;
                float c2 = (s     <= t2) ? acc[mi][ni][2] : 0.f;
                float c3 = (s + 1 <= t2) ? acc[mi][ni][3] : 0.f;
                *(__half2*)&sh[CA_A + t  * 136 + s] = __floats2half2_rn(c0, c1);
                *(__half2*)&sh[CA_A + t2 * 136 + s] = __floats2half2_rn(c2, c3);
            }
    }
    __syncthreads();

    // ---- denominators ----
    if (tid < CHUNK) {
        int t = tid;
        float den = EPSF;
        const __half2* qr = (const __half2*)&sh[CA_QF + t * 72];
#pragma unroll 8
        for (int d2 = 0; d2 < 32; d2++) {
            float2 q = __half22float2(qr[d2]);
            den += q.x * zf[2*d2] + q.y * zf[2*d2 + 1];
        }
        const __half2* ar = (const __half2*)&sh[CA_A + t * 136];
#pragma unroll 8
        for (int s2 = 0; s2 < 64; s2++) {
            float2 a = __half22float2(ar[s2]);
            den += a.x + a.y;
        }
        sdi[t] = 1.f / den;
    }
    __syncthreads();

    // ---- phase 2: out = (A V + Q Sh + Q Sl) * inv_den -> g_af fp16 ----
    {
        int wm = (wid & 1) * 64, wn = (wid >> 1) * 16;
        const int arow = lid & 15, acol = (lid >> 4) << 3;
        const int brow = lid & 7,  bcol = lid & 8;
        float acc[4][2][4];
#pragma unroll
        for (int mi = 0; mi < 4; mi++)
#pragma unroll
            for (int ni = 0; ni < 2; ni++)
#pragma unroll
                for (int kk = 0; kk < 4; kk++) acc[mi][ni][kk] = 0.f;

        // A V  (k = s): kt tiles with k0 > wm+63 are all-zero A -> skip
        const int ktmaxAV = wm / 16 + 4;     // wm=0 -> 4, wm=64 -> 8
        for (int kt = 0; kt < ktmaxAV; kt++) {
            int k0 = kt * 16;
            uint32_t ar[4][4], br[2][2];
#pragma unroll
            for (int mi = 0; mi < 4; mi++)
                ldsm_x4(ar[mi], sb + (CA_A + (wm + mi*16 + arow) * 136 + k0 + acol) * 2);
#pragma unroll
            for (int ni = 0; ni < 2; ni++)
                ldsm_x2(br[ni], sb + (CA_VT + (wn + ni*8 + brow) * 136 + k0 + bcol) * 2);
#pragma unroll
            for (int mi = 0; mi < 4; mi++)
#pragma unroll
                for (int ni = 0; ni < 2; ni++)
                    mma_f16(acc[mi][ni], ar[mi], br[ni]);
        }
        // Q S_hi + Q S_lo  (k = d, 4 tiles each)
#pragma unroll
        for (int pass = 0; pass < 2; pass++) {
            int stoff = pass ? CA_STL : CA_STH;
#pragma unroll
            for (int kt = 0; kt < 4; kt++) {
                int k0 = kt * 16;
                uint32_t ar[4][4], br[2][2];
#pragma unroll
                for (int mi = 0; mi < 4; mi++)
                    ldsm_x4(ar[mi], sb + (CA_QF + (wm + mi*16 + arow) * 72 + k0 + acol) * 2);
#pragma unroll
                for (int ni = 0; ni < 2; ni++)
                    ldsm_x2(br[ni], sb + (stoff + (wn + ni*8 + brow) * 72 + k0 + bcol) * 2);
#pragma unroll
                for (int mi = 0; mi < 4; mi++)
#pragma unroll
                    for (int ni = 0; ni < 2; ni++)
                        mma_f16(acc[mi][ni], ar[mi], br[ni]);
            }
        }

        int er = lid >> 2, ec = (lid & 3) * 2;
#pragma unroll
        for (int mi = 0; mi < 4; mi++)
#pragma unroll
            for (int ni = 0; ni < 2; ni++) {
                int t = wm + mi * 16 + er, e = wn + ni * 8 + ec;
                float i0 = sdi[t], i1 = sdi[t + 8];
                *(__half2*)&g_af[base + (size_t)t * EE + e] =
                    __floats2half2_rn(acc[mi][ni][0] * i0, acc[mi][ni][1] * i0);
                *(__half2*)&g_af[base + (size_t)(t + 8) * EE + e] =
                    __floats2half2_rn(acc[mi][ni][2] * i1, acc[mi][ni][3] * i1);
            }
    }
}

// ---------------- host ----------------------------------------------------------
extern "C" void kernel_launch(void* const* d_in, const int* in_sizes, int n_in,
                              void* d_out, int out_size)
{
    const float* x  = (const float*)d_in[0];
    const float* Wq = (const float*)d_in[1];
    const float* bq = (const float*)d_in[2];
    const float* Wk = (const float*)d_in[3];
    const float* bk = (const float*)d_in[4];
    const float* Wv = (const float*)d_in[5];
    const float* bv = (const float*)d_in[6];
    const float* Wo = (const float*)d_in[7];
    const float* bo = (const float*)d_in[8];
    float* out = (float*)d_out;

    __half *xf, *qf, *kf, *vf, *af, *wf;
    cudaGetSymbolAddress((void**)&xf, g_xf);
    cudaGetSymbolAddress((void**)&qf, g_qf);
    cudaGetSymbolAddress((void**)&kf, g_kf);
    cudaGetSymbolAddress((void**)&vf, g_vf);
    cudaGetSymbolAddress((void**)&af, g_af);
    cudaGetSymbolAddress((void**)&wf, g_wf);

    cudaFuncSetAttribute(gemm_f16<0>, cudaFuncAttributeMaxDynamicSharedMemorySize, GSM_BYTES);
    cudaFuncSetAttribute(gemm_f16<1>, cudaFuncAttributeMaxDynamicSharedMemorySize, GSM_BYTES);
    cudaFuncSetAttribute(chunk_sums_kernel,
                         cudaFuncAttributeMaxDynamicSharedMemorySize, 2 * 64 * 136 * 2);
    cudaFuncSetAttribute(chunk_attn_kernel,
                         cudaFuncAttributeMaxDynamicSharedMemorySize, CA_BYTES);

    // fused converts: x + 4 weights in one launch
    int total4 = XN4 + 4 * WN4;
    cvt_all_kernel<<<(total4 + 255) / 256, 256>>>(x, Wq, Wk, Wv, Wo, xf, wf);

    // fused QKV projection -> fp16 q/k/v with elu+1 on q,k
    dim3 gq(MROWS / 128, 12);
    gemm_f16<1><<<gq, 256, GSM_BYTES>>>(xf, wf, bq, bk, bv, qf, kf, vf, 0x3);

    chunk_sums_kernel<<<NBH * NCH, 256, 2 * 64 * 136 * 2>>>();

    int totalPref = NBH * (DD * DD + DD);
    prefix_kernel<<<(totalPref + 255) / 256, 256>>>();

    chunk_attn_kernel<<<NBH * NCH, 256, CA_BYTES>>>();

    // output projection -> fp32 d_out
    dim3 go(MROWS / 128, 4);
    gemm_f16<0><<<go, 256, GSM_BYTES>>>(af, wf + 3*WSZ, bo, bo, bo, out, out, out, 0x0);
}

// round 16
// speedup vs baseline: 1.4209x; 1.4018x over previous
#include <cuda_runtime.h>
#include <cuda_fp16.h>
#include <math.h>
#include <stdint.h>

#define BB 2
#define TT 4096
#define EE 512
#define HH 8
#define DD 64
#define CHUNK 128
#define NCH (TT/CHUNK)     // 32
#define NBH (BB*HH)        // 16
#define EPSF 1e-6f
#define MROWS (BB*TT)      // 8192
#define WSZ (EE*EE)

// ---------------- scratch (__device__ globals) ---------------------------------
__device__ float g_Mc[NBH*NCH*DD*DD];
__device__ float g_zc[NBH*NCH*DD];
__device__ float g_Mp[NBH*NCH*DD*DD];
__device__ float g_zp[NBH*NCH*DD];

__device__ __half g_xf[MROWS*EE];
__device__ __half g_qf[MROWS*EE];
__device__ __half g_kf[MROWS*EE];
__device__ __half g_vf[MROWS*EE];
__device__ __half g_af[MROWS*EE];
__device__ __half g_wf[4*WSZ];

// ---------------- helpers -------------------------------------------------------
__device__ __forceinline__ uint32_t smem_u32(const void* p) {
    uint32_t a;
    asm("{ .reg .u64 t; cvta.to.shared.u64 t, %1; cvt.u32.u64 %0, t; }"
        : "=r"(a) : "l"(p));
    return a;
}

#define SWZ128(x) ((x) ^ (((x) >> 3) & 0x70))

__device__ __forceinline__ void cp16(uint32_t dst, const void* src) {
    asm volatile("cp.async.cg.shared.global [%0], [%1], 16;" :: "r"(dst), "l"(src));
}
__device__ __forceinline__ void cp_commit() {
    asm volatile("cp.async.commit_group;" ::: "memory");
}
__device__ __forceinline__ void cp_wait0() {
    asm volatile("cp.async.wait_group 0;" ::: "memory");
}

__device__ __forceinline__ void ldsm_x4(uint32_t r[4], uint32_t addr) {
    asm volatile("ldmatrix.sync.aligned.m8n8.x4.shared.b16 {%0,%1,%2,%3}, [%4];"
                 : "=r"(r[0]), "=r"(r[1]), "=r"(r[2]), "=r"(r[3]) : "r"(addr));
}
__device__ __forceinline__ void ldsm_x2(uint32_t r[2], uint32_t addr) {
    asm volatile("ldmatrix.sync.aligned.m8n8.x2.shared.b16 {%0,%1}, [%2];"
                 : "=r"(r[0]), "=r"(r[1]) : "r"(addr));
}
__device__ __forceinline__ void mma_f16(float c[4], const uint32_t a[4], const uint32_t b[2]) {
    asm volatile(
        "mma.sync.aligned.m16n8k16.row.col.f32.f16.f16.f32 "
        "{%0,%1,%2,%3}, {%4,%5,%6,%7}, {%8,%9}, {%0,%1,%2,%3};"
        : "+f"(c[0]), "+f"(c[1]), "+f"(c[2]), "+f"(c[3])
        : "r"(a[0]), "r"(a[1]), "r"(a[2]), "r"(a[3]), "r"(b[0]), "r"(b[1]));
}

// ---------------- convert: fp32 -> fp16 (x + 4 weights, one launch) -------------
#define XN4 (MROWS*EE/4)      // 1048576
#define WN4 (WSZ/4)           // 65536
__global__ __launch_bounds__(256) void cvt_all_kernel(
    const float* __restrict__ x,
    const float* __restrict__ w0, const float* __restrict__ w1,
    const float* __restrict__ w2, const float* __restrict__ w3,
    __half* __restrict__ xf, __half* __restrict__ wf)
{
    int i = blockIdx.x * 256 + threadIdx.x;
    const float* s;
    __half2* dp;
    int j;
    if (i < XN4) {
        s = x; dp = (__half2*)xf; j = i;
    } else {
        int k = i - XN4;
        int g = k / WN4;
        j = k - g * WN4;
        s = (g == 0) ? w0 : (g == 1) ? w1 : (g == 2) ? w2 : w3;
        dp = (__half2*)(wf + (size_t)g * WSZ);
    }
    float4 v = ((const float4*)s)[j];
    dp[j*2+0] = __floats2half2_rn(v.x, v.y);
    dp[j*2+1] = __floats2half2_rn(v.z, v.w);
}

// ---------------- mma.sync fp16 GEMM, cp.async double-buffered ------------------
#define OF_A 0
#define OF_B 16384
#define STAGE_BYTES 32768
#define OF_BIAS (2*STAGE_BYTES)
#define GSM_BYTES (2*STAGE_BYTES + 512 + 256)

template<int F16OUT>
__global__ __launch_bounds__(256, 2) void gemm_f16(
    const __half* __restrict__ Af, const __half* __restrict__ Wf,
    const float* b0, const float* b1, const float* b2,
    void* Y0, void* Y1, void* Y2, int actmask)
{
    extern __shared__ char smem_raw[];
    uint32_t sb0 = smem_u32(smem_raw);
    uint32_t sb  = (sb0 + 127) & ~127u;
    char* smb = smem_raw + (sb - sb0);

    const int tid = threadIdx.x, lid = tid & 31, wid = tid >> 5;
    const int wm = (wid & 1) * 64;
    const int wn = (wid >> 1) * 32;
    const int g  = blockIdx.y >> 2;
    const int m0 = blockIdx.x * 128, n0 = (blockIdx.y & 3) * 128;

    const __half* Bf = Wf + (size_t)g * WSZ;
    const float* bias = (g == 0) ? b0 : (g == 1) ? b1 : b2;
    void* Yv = (g == 0) ? Y0 : (g == 1) ? Y1 : Y2;
    const bool act = (actmask >> g) & 1;

    float* sbias = (float*)(smb + OF_BIAS);
    if (tid < 128) sbias[tid] = bias[n0 + tid];

    float acc[4][4][4];
#pragma unroll
    for (int mi = 0; mi < 4; mi++)
#pragma unroll
        for (int ni = 0; ni < 4; ni++)
#pragma unroll
            for (int kk = 0; kk < 4; kk++) acc[mi][ni][kk] = 0.f;

    const int arow = wm + (lid & 15);
    const int acolb = (lid >> 4) << 3;
    const int brow = wn + (lid & 7);
    const int bcolb = (lid & 8);

    const int lrow = tid >> 3, lj = tid & 7;
#define ISSUE_LOAD(st, k0) do {                                                   \
    uint32_t base = sb + (st) * STAGE_BYTES;                                      \
    _Pragma("unroll")                                                             \
    for (int p = 0; p < 4; p++) {                                                 \
        int row = lrow + p * 32;                                                  \
        uint32_t off = SWZ128((uint32_t)(row * 128 + lj * 16));                   \
        cp16(base + OF_A + off, Af + (size_t)(m0 + row) * EE + (k0) + lj * 8);    \
        cp16(base + OF_B + off, Bf + (size_t)(n0 + row) * EE + (k0) + lj * 8);    \
    }                                                                             \
    cp_commit();                                                                  \
} while (0)

    ISSUE_LOAD(0, 0);
    int cur = 0;
    for (int c = 0; c < 8; c++) {
        cp_wait0();
        __syncthreads();
        if (c < 7) ISSUE_LOAD(cur ^ 1, (c + 1) * 64);

        uint32_t tb = sb + cur * STAGE_BYTES;
#pragma unroll
        for (int ks = 0; ks < 4; ks++) {
            uint32_t ar[4][4], br[4][2];
            int ak = ks * 16 + acolb;
#pragma unroll
            for (int mi = 0; mi < 4; mi++) {
                uint32_t off = SWZ128((uint32_t)((arow + mi * 16) * 128 + ak * 2));
                ldsm_x4(ar[mi], tb + OF_A + off);
            }
            int bk = ks * 16 + bcolb;
#pragma unroll
            for (int ni = 0; ni < 4; ni++) {
                uint32_t off = SWZ128((uint32_t)((brow + ni * 8) * 128 + bk * 2));
                ldsm_x2(br[ni], tb + OF_B + off);
            }
#pragma unroll
            for (int mi = 0; mi < 4; mi++)
#pragma unroll
                for (int ni = 0; ni < 4; ni++)
                    mma_f16(acc[mi][ni], ar[mi], br[ni]);
        }
        cur ^= 1;
    }
#undef ISSUE_LOAD

    const int er = lid >> 2, ec = (lid & 3) * 2;
#pragma unroll
    for (int mi = 0; mi < 4; mi++) {
#pragma unroll
        for (int ni = 0; ni < 4; ni++) {
            int nn = wn + ni * 8 + ec;
            float bb0 = sbias[nn], bb1 = sbias[nn + 1];
            int m1 = m0 + wm + mi * 16 + er;
            float2 v0 = make_float2(acc[mi][ni][0] + bb0, acc[mi][ni][1] + bb1);
            float2 v1 = make_float2(acc[mi][ni][2] + bb0, acc[mi][ni][3] + bb1);
            if (act) {
                v0.x = (v0.x > 0.f) ? (v0.x + 1.f) : expf(v0.x);
                v0.y = (v0.y > 0.f) ? (v0.y + 1.f) : expf(v0.y);
                v1.x = (v1.x > 0.f) ? (v1.x + 1.f) : expf(v1.x);
                v1.y = (v1.y > 0.f) ? (v1.y + 1.f) : expf(v1.y);
            }
            if (F16OUT) {
                __half* Y = (__half*)Yv;
                *(__half2*)&Y[(size_t)m1 * EE + n0 + nn]       = __floats2half2_rn(v0.x, v0.y);
                *(__half2*)&Y[(size_t)(m1 + 8) * EE + n0 + nn] = __floats2half2_rn(v1.x, v1.y);
            } else {
                float* Y = (float*)Yv;
                *(float2*)&Y[(size_t)m1 * EE + n0 + nn] = v0;
                *(float2*)&Y[(size_t)(m1 + 8) * EE + n0 + nn] = v1;
            }
        }
    }
}

// ---------------- Pass A: Mc = K^T V + z via mma --------------------------------
__global__ __launch_bounds__(256) void chunk_sums_kernel()
{
    int blk = blockIdx.x;
    int bh = blk / NCH, c = blk % NCH;
    int b = bh / HH, h = bh % HH;

    extern __shared__ __half sh[];
    __half* KT = sh;
    __half* VT = sh + 64 * 136;
    int tid = threadIdx.x;
    size_t base = ((size_t)b * TT + (size_t)c * CHUNK) * EE + h * DD;

    for (int i = tid; i < 128 * 32; i += 256) {
        int e2 = i & 31, t = i >> 5;
        __half2 kv = *(const __half2*)&g_kf[base + (size_t)t * EE + e2 * 2];
        __half2 vv = *(const __half2*)&g_vf[base + (size_t)t * EE + e2 * 2];
        KT[(2*e2) * 136 + t] = __low2half(kv);  KT[(2*e2+1) * 136 + t] = __high2half(kv);
        VT[(2*e2) * 136 + t] = __low2half(vv);  VT[(2*e2+1) * 136 + t] = __high2half(vv);
    }
    __syncthreads();

    uint32_t sb = smem_u32(sh);
    int lid = tid & 31, wid = tid >> 5;
    int wm = (wid & 1) * 32, wn = (wid >> 1) * 16;
    float acc[2][2][4];
#pragma unroll
    for (int mi = 0; mi < 2; mi++)
#pragma unroll
        for (int ni = 0; ni < 2; ni++)
#pragma unroll
            for (int kk = 0; kk < 4; kk++) acc[mi][ni][kk] = 0.f;

    const int arow = lid & 15, acol = (lid >> 4) << 3;
    const int brow = lid & 7,  bcol = lid & 8;

#pragma unroll
    for (int kt = 0; kt < 8; kt++) {
        int k0 = kt * 16;
        uint32_t ar[2][4], br[2][2];
#pragma unroll
        for (int mi = 0; mi < 2; mi++)
            ldsm_x4(ar[mi], sb + ((wm + mi*16 + arow) * 136 + k0 + acol) * 2);
#pragma unroll
        for (int ni = 0; ni < 2; ni++)
            ldsm_x2(br[ni], sb + (64*136 + (wn + ni*8 + brow) * 136 + k0 + bcol) * 2);
#pragma unroll
        for (int mi = 0; mi < 2; mi++)
#pragma unroll
            for (int ni = 0; ni < 2; ni++)
                mma_f16(acc[mi][ni], ar[mi], br[ni]);
    }

    int er = lid >> 2, ec = (lid & 3) * 2;
    float* Mout = g_Mc + (size_t)blk * DD * DD;
#pragma unroll
    for (int mi = 0; mi < 2; mi++)
#pragma unroll
        for (int ni = 0; ni < 2; ni++) {
            int d = wm + mi * 16 + er, e = wn + ni * 8 + ec;
            *(float2*)&Mout[d * DD + e]       = make_float2(acc[mi][ni][0], acc[mi][ni][1]);
            *(float2*)&Mout[(d + 8) * DD + e] = make_float2(acc[mi][ni][2], acc[mi][ni][3]);
        }

    if (tid < DD) {
        float zz = 0.f;
        const __half2* row = (const __half2*)&KT[tid * 136];
#pragma unroll 8
        for (int t2 = 0; t2 < 64; t2++) {
            float2 f = __half22float2(row[t2]);
            zz += f.x + f.y;
        }
        g_zc[(size_t)blk * DD + tid] = zz;
    }
}

// ---------------- Pass B: exclusive prefix over chunks (simple serial) ----------
__global__ void prefix_kernel()
{
    int idx = blockIdx.x * 256 + threadIdx.x;
    const int PER = DD * DD + DD;
    if (idx >= NBH * PER) return;
    int bh = idx / PER;
    int r  = idx % PER;
    if (r < DD * DD) {
        float run = 0.f;
        for (int c = 0; c < NCH; c++) {
            size_t o = (size_t)(bh * NCH + c) * DD * DD + r;
            g_Mp[o] = run;
            run += g_Mc[o];
        }
    } else {
        int d = r - DD * DD;
        float run = 0.f;
        for (int c = 0; c < NCH; c++) {
            size_t o = (size_t)(bh * NCH + c) * DD + d;
            g_zp[o] = run;
            run += g_zc[o];
        }
    }
}

// ---------------- Pass C: tensorized intra-chunk attention ----------------------
#define CA_QF 0
#define CA_KF 9216
#define CA_VT 18432
#define CA_STH 27136
#define CA_STL 31744
#define CA_A  36352
#define CA_ZB 107520
#define CA_DIB 107776
#define CA_BYTES 108544

__global__ __launch_bounds__(256, 1) void chunk_attn_kernel()
{
    int blk = blockIdx.x;
    int bh = blk / NCH, c = blk % NCH;
    int b = bh / HH, h = bh % HH;

    extern __shared__ char smc[];
    __half* sh = (__half*)smc;
    float* zf  = (float*)(smc + CA_ZB);
    float* sdi = (float*)(smc + CA_DIB);
    uint32_t sb = smem_u32(smc);

    int tid = threadIdx.x, lid = tid & 31, wid = tid >> 5;
    size_t base = ((size_t)b * TT + (size_t)c * CHUNK) * EE + h * DD;
    const float* Mp = g_Mp + (size_t)blk * DD * DD;
    const float* zp = g_zp + (size_t)blk * DD;

    // q,k row-major fp16
    for (int i = tid; i < 128 * 8; i += 256) {
        int row = i >> 3, j = i & 7;
        *(uint4*)&sh[CA_QF + row * 72 + j * 8] =
            *(const uint4*)&g_qf[base + (size_t)row * EE + j * 8];
        *(uint4*)&sh[CA_KF + row * 72 + j * 8] =
            *(const uint4*)&g_kf[base + (size_t)row * EE + j * 8];
    }
    // V transposed (coalesced loads, conflicted stores — measured faster)
    for (int i = tid; i < 128 * 32; i += 256) {
        int e2 = i & 31, t = i >> 5;
        __half2 vv = *(const __half2*)&g_vf[base + (size_t)t * EE + e2 * 2];
        sh[CA_VT + (2*e2) * 136 + t] = __low2half(vv);
        sh[CA_VT + (2*e2+1) * 136 + t] = __high2half(vv);
    }
    // S^T hi/lo
    for (int i = tid; i < 64 * 16; i += 256) {
        int d = i >> 4, e4 = (i & 15) * 4;
        float4 s4 = *(const float4*)&Mp[d * DD + e4];
        float fs[4] = {s4.x, s4.y, s4.z, s4.w};
#pragma unroll
        for (int j = 0; j < 4; j++) {
            __half hi = __float2half(fs[j]);
            sh[CA_STH + (e4 + j) * 72 + d] = hi;
            sh[CA_STL + (e4 + j) * 72 + d] = __float2half(fs[j] - __half2float(hi));
        }
    }
    if (tid < DD) zf[tid] = zp[tid];
    __syncthreads();

    // ---- phase 1: A = Q K^T (causal-masked), fp16 into smem ----
    {
        int wm = (wid & 1) * 64, wn = (wid >> 1) * 32;
        const int arow = lid & 15, acol = (lid >> 4) << 3;
        const int brow = lid & 7,  bcol = lid & 8;
        float acc[4][4][4];
#pragma unroll
        for (int mi = 0; mi < 4; mi++)
#pragma unroll
            for (int ni = 0; ni < 4; ni++)
#pragma unroll
                for (int kk = 0; kk < 4; kk++) acc[mi][ni][kk] = 0.f;

        // skip warps whose whole 64x32 tile is above the diagonal (A==0 there)
        if (wn <= wm + 63) {
#pragma unroll
            for (int kt = 0; kt < 4; kt++) {
                int k0 = kt * 16;
                uint32_t ar[4][4], br[4][2];
#pragma unroll
                for (int mi = 0; mi < 4; mi++)
                    ldsm_x4(ar[mi], sb + (CA_QF + (wm + mi*16 + arow) * 72 + k0 + acol) * 2);
#pragma unroll
                for (int ni = 0; ni < 4; ni++)
                    ldsm_x2(br[ni], sb + (CA_KF + (wn + ni*8 + brow) * 72 + k0 + bcol) * 2);
#pragma unroll
                for (int mi = 0; mi < 4; mi++)
#pragma unroll
                    for (int ni = 0; ni < 4; ni++)
                        if (wn + ni * 8 <= wm + mi * 16 + 15)   // subtile touches diag
                            mma_f16(acc[mi][ni], ar[mi], br[ni]);
            }
        }

        int er = lid >> 2, ec = (lid & 3) * 2;
#pragma unroll
        for (int mi = 0; mi < 4; mi++)
#pragma unroll
            for (int ni = 0; ni < 4; ni++) {
                int t = wm + mi * 16 + er, s = wn + ni * 8 + ec;
                float c0 = (s     <= t) ? acc[mi][ni][0] : 0.f;
                float c1 = (s + 1 <= t) ? acc[mi][ni][1] : 0.f;
                int t2 = t + 8;
                float c2 = (s     <= t2) ? acc[mi][ni][2] : 0.f;
                float c3 = (s + 1 <= t2) ? acc[mi][ni][3] : 0.f;
                *(__half2*)&sh[CA_A + t  * 136 + s] = __floats2half2_rn(c0, c1);
                *(__half2*)&sh[CA_A + t2 * 136 + s] = __floats2half2_rn(c2, c3);
            }
    }
    __syncthreads();

    // ---- denominators ----
    if (tid < CHUNK) {
        int t = tid;
        float den = EPSF;
        const __half2* qr = (const __half2*)&sh[CA_QF + t * 72];
#pragma unroll 8
        for (int d2 = 0; d2 < 32; d2++) {
            float2 q = __half22float2(qr[d2]);
            den += q.x * zf[2*d2] + q.y * zf[2*d2 + 1];
        }
        const __half2* ar = (const __half2*)&sh[CA_A + t * 136];
#pragma unroll 8
        for (int s2 = 0; s2 < 64; s2++) {
            float2 a = __half22float2(ar[s2]);
            den += a.x + a.y;
        }
        sdi[t] = 1.f / den;
    }
    __syncthreads();

    // ---- phase 2: out = (A V + Q Sh + Q Sl) * inv_den -> g_af fp16 ----
    {
        int wm = (wid & 1) * 64, wn = (wid >> 1) * 16;
        const int arow = lid & 15, acol = (lid >> 4) << 3;
        const int brow = lid & 7,  bcol = lid & 8;
        float acc[4][2][4];
#pragma unroll
        for (int mi = 0; mi < 4; mi++)
#pragma unroll
            for (int ni = 0; ni < 2; ni++)
#pragma unroll
                for (int kk = 0; kk < 4; kk++) acc[mi][ni][kk] = 0.f;

        // A V  (k = s): kt tiles with k0 > wm+63 are all-zero A -> skip
        const int ktmaxAV = wm / 16 + 4;     // wm=0 -> 4, wm=64 -> 8
        for (int kt = 0; kt < ktmaxAV; kt++) {
            int k0 = kt * 16;
            uint32_t ar[4][4], br[2][2];
#pragma unroll
            for (int mi = 0; mi < 4; mi++)
                ldsm_x4(ar[mi], sb + (CA_A + (wm + mi*16 + arow) * 136 + k0 + acol) * 2);
#pragma unroll
            for (int ni = 0; ni < 2; ni++)
                ldsm_x2(br[ni], sb + (CA_VT + (wn + ni*8 + brow) * 136 + k0 + bcol) * 2);
#pragma unroll
            for (int mi = 0; mi < 4; mi++)
#pragma unroll
                for (int ni = 0; ni < 2; ni++)
                    mma_f16(acc[mi][ni], ar[mi], br[ni]);
        }
        // Q S_hi + Q S_lo  (k = d, 4 tiles each)
#pragma unroll
        for (int pass = 0; pass < 2; pass++) {
            int stoff = pass ? CA_STL : CA_STH;
#pragma unroll
            for (int kt = 0; kt < 4; kt++) {
                int k0 = kt * 16;
                uint32_t ar[4][4], br[2][2];
#pragma unroll
                for (int mi = 0; mi < 4; mi++)
                    ldsm_x4(ar[mi], sb + (CA_QF + (wm + mi*16 + arow) * 72 + k0 + acol) * 2);
#pragma unroll
                for (int ni = 0; ni < 2; ni++)
                    ldsm_x2(br[ni], sb + (stoff + (wn + ni*8 + brow) * 72 + k0 + bcol) * 2);
#pragma unroll
                for (int mi = 0; mi < 4; mi++)
#pragma unroll
                    for (int ni = 0; ni < 2; ni++)
                        mma_f16(acc[mi][ni], ar[mi], br[ni]);
            }
        }

        int er = lid >> 2, ec = (lid & 3) * 2;
#pragma unroll
        for (int mi = 0; mi < 4; mi++)
#pragma unroll
            for (int ni = 0; ni < 2; ni++) {
                int t = wm + mi * 16 + er, e = wn + ni * 8 + ec;
                float i0 = sdi[t], i1 = sdi[t + 8];
                *(__half2*)&g_af[base + (size_t)t * EE + e] =
                    __floats2half2_rn(acc[mi][ni][0] * i0, acc[mi][ni][1] * i0);
                *(__half2*)&g_af[base + (size_t)(t + 8) * EE + e] =
                    __floats2half2_rn(acc[mi][ni][2] * i1, acc[mi][ni][3] * i1);
            }
    }
}

// ---------------- host ----------------------------------------------------------
extern "C" void kernel_launch(void* const* d_in, const int* in_sizes, int n_in,
                              void* d_out, int out_size)
{
    const float* x  = (const float*)d_in[0];
    const float* Wq = (const float*)d_in[1];
    const float* bq = (const float*)d_in[2];
    const float* Wk = (const float*)d_in[3];
    const float* bk = (const float*)d_in[4];
    const float* Wv = (const float*)d_in[5];
    const float* bv = (const float*)d_in[6];
    const float* Wo = (const float*)d_in[7];
    const float* bo = (const float*)d_in[8];
    float* out = (float*)d_out;

    __half *xf, *qf, *kf, *vf, *af, *wf;
    cudaGetSymbolAddress((void**)&xf, g_xf);
    cudaGetSymbolAddress((void**)&qf, g_qf);
    cudaGetSymbolAddress((void**)&kf, g_kf);
    cudaGetSymbolAddress((void**)&vf, g_vf);
    cudaGetSymbolAddress((void**)&af, g_af);
    cudaGetSymbolAddress((void**)&wf, g_wf);

    cudaFuncSetAttribute(gemm_f16<0>, cudaFuncAttributeMaxDynamicSharedMemorySize, GSM_BYTES);
    cudaFuncSetAttribute(gemm_f16<1>, cudaFuncAttributeMaxDynamicSharedMemorySize, GSM_BYTES);
    cudaFuncSetAttribute(chunk_sums_kernel,
                         cudaFuncAttributeMaxDynamicSharedMemorySize, 2 * 64 * 136 * 2);
    cudaFuncSetAttribute(chunk_attn_kernel,
                         cudaFuncAttributeMaxDynamicSharedMemorySize, CA_BYTES);

    // fused converts: x + 4 weights in one launch
    int total4 = XN4 + 4 * WN4;
    cvt_all_kernel<<<(total4 + 255) / 256, 256>>>(x, Wq, Wk, Wv, Wo, xf, wf);

    // fused QKV projection -> fp16 q/k/v with elu+1 on q,k
    dim3 gq(MROWS / 128, 12);
    gemm_f16<1><<<gq, 256, GSM_BYTES>>>(xf, wf, bq, bk, bv, qf, kf, vf, 0x3);

    chunk_sums_kernel<<<NBH * NCH, 256, 2 * 64 * 136 * 2>>>();

    int totalPref = NBH * (DD * DD + DD);
    prefix_kernel<<<(totalPref + 255) / 256, 256>>>();

    chunk_attn_kernel<<<NBH * NCH, 256, CA_BYTES>>>();

    // output projection -> fp32 d_out
    dim3 go(MROWS / 128, 4);
    gemm_f16<0><<<go, 256, GSM_BYTES>>>(af, wf + 3*WSZ, bo, bo, bo, out, out, out, 0x0);
}

// round 17
// speedup vs baseline: 1.4820x; 1.0430x over previous
#include <cuda_runtime.h>
#include <cuda_fp16.h>
#include <math.h>
#include <stdint.h>

#define BB 2
#define TT 4096
#define EE 512
#define HH 8
#define DD 64
#define CHUNK 128
#define NCH (TT/CHUNK)     // 32
#define NBH (BB*HH)        // 16
#define EPSF 1e-6f
#define MROWS (BB*TT)      // 8192
#define WSZ (EE*EE)

// ---------------- scratch (__device__ globals) ---------------------------------
__device__ float g_Mc[NBH*NCH*DD*DD];
__device__ float g_zc[NBH*NCH*DD];
__device__ float g_Mp[NBH*NCH*DD*DD];
__device__ float g_zp[NBH*NCH*DD];

__device__ __half g_xf[MROWS*EE];
__device__ __half g_qf[MROWS*EE];
__device__ __half g_kf[MROWS*EE];
__device__ __half g_vf[MROWS*EE];
__device__ __half g_af[MROWS*EE];
__device__ __half g_wf[4*WSZ];

// ---------------- helpers -------------------------------------------------------
__device__ __forceinline__ uint32_t smem_u32(const void* p) {
    uint32_t a;
    asm("{ .reg .u64 t; cvta.to.shared.u64 t, %1; cvt.u32.u64 %0, t; }"
        : "=r"(a) : "l"(p));
    return a;
}

#define SWZ128(x) ((x) ^ (((x) >> 3) & 0x70))

__device__ __forceinline__ void cp16(uint32_t dst, const void* src) {
    asm volatile("cp.async.cg.shared.global [%0], [%1], 16;" :: "r"(dst), "l"(src));
}
__device__ __forceinline__ void cp_commit() {
    asm volatile("cp.async.commit_group;" ::: "memory");
}
__device__ __forceinline__ void cp_wait0() {
    asm volatile("cp.async.wait_group 0;" ::: "memory");
}

__device__ __forceinline__ void ldsm_x4(uint32_t r[4], uint32_t addr) {
    asm volatile("ldmatrix.sync.aligned.m8n8.x4.shared.b16 {%0,%1,%2,%3}, [%4];"
                 : "=r"(r[0]), "=r"(r[1]), "=r"(r[2]), "=r"(r[3]) : "r"(addr));
}
__device__ __forceinline__ void ldsm_x2(uint32_t r[2], uint32_t addr) {
    asm volatile("ldmatrix.sync.aligned.m8n8.x2.shared.b16 {%0,%1}, [%2];"
                 : "=r"(r[0]), "=r"(r[1]) : "r"(addr));
}
__device__ __forceinline__ void mma_f16(float c[4], const uint32_t a[4], const uint32_t b[2]) {
    asm volatile(
        "mma.sync.aligned.m16n8k16.row.col.f32.f16.f16.f32 "
        "{%0,%1,%2,%3}, {%4,%5,%6,%7}, {%8,%9}, {%0,%1,%2,%3};"
        : "+f"(c[0]), "+f"(c[1]), "+f"(c[2]), "+f"(c[3])
        : "r"(a[0]), "r"(a[1]), "r"(a[2]), "r"(a[3]), "r"(b[0]), "r"(b[1]));
}

// ---------------- convert: fp32 -> fp16 (x + 4 weights, one launch) -------------
#define XN4 (MROWS*EE/4)      // 1048576
#define WN4 (WSZ/4)           // 65536
__global__ __launch_bounds__(256) void cvt_all_kernel(
    const float* __restrict__ x,
    const float* __restrict__ w0, const float* __restrict__ w1,
    const float* __restrict__ w2, const float* __restrict__ w3,
    __half* __restrict__ xf, __half* __restrict__ wf)
{
    int i = blockIdx.x * 256 + threadIdx.x;
    const float* s;
    __half2* dp;
    int j;
    if (i < XN4) {
        s = x; dp = (__half2*)xf; j = i;
    } else {
        int k = i - XN4;
        int g = k / WN4;
        j = k - g * WN4;
        s = (g == 0) ? w0 : (g == 1) ? w1 : (g == 2) ? w2 : w3;
        dp = (__half2*)(wf + (size_t)g * WSZ);
    }
    float4 v = ((const float4*)s)[j];
    dp[j*2+0] = __floats2half2_rn(v.x, v.y);
    dp[j*2+1] = __floats2half2_rn(v.z, v.w);
}

// ---------------- mma.sync fp16 GEMM, cp.async double-buffered ------------------
#define OF_A 0
#define OF_B 16384
#define STAGE_BYTES 32768
#define OF_BIAS (2*STAGE_BYTES)
#define GSM_BYTES (2*STAGE_BYTES + 512 + 256)

template<int F16OUT>
__global__ __launch_bounds__(256, 2) void gemm_f16(
    const __half* __restrict__ Af, const __half* __restrict__ Wf,
    const float* b0, const float* b1, const float* b2,
    void* Y0, void* Y1, void* Y2, int actmask)
{
    extern __shared__ char smem_raw[];
    uint32_t sb0 = smem_u32(smem_raw);
    uint32_t sb  = (sb0 + 127) & ~127u;
    char* smb = smem_raw + (sb - sb0);

    const int tid = threadIdx.x, lid = tid & 31, wid = tid >> 5;
    const int wm = (wid & 1) * 64;
    const int wn = (wid >> 1) * 32;
    const int g  = blockIdx.y >> 2;
    const int m0 = blockIdx.x * 128, n0 = (blockIdx.y & 3) * 128;

    const __half* Bf = Wf + (size_t)g * WSZ;
    const float* bias = (g == 0) ? b0 : (g == 1) ? b1 : b2;
    void* Yv = (g == 0) ? Y0 : (g == 1) ? Y1 : Y2;
    const bool act = (actmask >> g) & 1;

    float* sbias = (float*)(smb + OF_BIAS);
    if (tid < 128) sbias[tid] = bias[n0 + tid];

    float acc[4][4][4];
#pragma unroll
    for (int mi = 0; mi < 4; mi++)
#pragma unroll
        for (int ni = 0; ni < 4; ni++)
#pragma unroll
            for (int kk = 0; kk < 4; kk++) acc[mi][ni][kk] = 0.f;

    const int arow = wm + (lid & 15);
    const int acolb = (lid >> 4) << 3;
    const int brow = wn + (lid & 7);
    const int bcolb = (lid & 8);

    const int lrow = tid >> 3, lj = tid & 7;
#define ISSUE_LOAD(st, k0) do {                                                   \
    uint32_t base = sb + (st) * STAGE_BYTES;                                      \
    _Pragma("unroll")                                                             \
    for (int p = 0; p < 4; p++) {                                                 \
        int row = lrow + p * 32;                                                  \
        uint32_t off = SWZ128((uint32_t)(row * 128 + lj * 16));                   \
        cp16(base + OF_A + off, Af + (size_t)(m0 + row) * EE + (k0) + lj * 8);    \
        cp16(base + OF_B + off, Bf + (size_t)(n0 + row) * EE + (k0) + lj * 8);    \
    }                                                                             \
    cp_commit();                                                                  \
} while (0)

    ISSUE_LOAD(0, 0);
    int cur = 0;
    for (int c = 0; c < 8; c++) {
        cp_wait0();
        __syncthreads();
        if (c < 7) ISSUE_LOAD(cur ^ 1, (c + 1) * 64);

        uint32_t tb = sb + cur * STAGE_BYTES;
#pragma unroll
        for (int ks = 0; ks < 4; ks++) {
            uint32_t ar[4][4], br[4][2];
            int ak = ks * 16 + acolb;
#pragma unroll
            for (int mi = 0; mi < 4; mi++) {
                uint32_t off = SWZ128((uint32_t)((arow + mi * 16) * 128 + ak * 2));
                ldsm_x4(ar[mi], tb + OF_A + off);
            }
            int bk = ks * 16 + bcolb;
#pragma unroll
            for (int ni = 0; ni < 4; ni++) {
                uint32_t off = SWZ128((uint32_t)((brow + ni * 8) * 128 + bk * 2));
                ldsm_x2(br[ni], tb + OF_B + off);
            }
#pragma unroll
            for (int mi = 0; mi < 4; mi++)
#pragma unroll
                for (int ni = 0; ni < 4; ni++)
                    mma_f16(acc[mi][ni], ar[mi], br[ni]);
        }
        cur ^= 1;
    }
#undef ISSUE_LOAD

    const int er = lid >> 2, ec = (lid & 3) * 2;
#pragma unroll
    for (int mi = 0; mi < 4; mi++) {
#pragma unroll
        for (int ni = 0; ni < 4; ni++) {
            int nn = wn + ni * 8 + ec;
            float bb0 = sbias[nn], bb1 = sbias[nn + 1];
            int m1 = m0 + wm + mi * 16 + er;
            float2 v0 = make_float2(acc[mi][ni][0] + bb0, acc[mi][ni][1] + bb1);
            float2 v1 = make_float2(acc[mi][ni][2] + bb0, acc[mi][ni][3] + bb1);
            if (act) {
                v0.x = (v0.x > 0.f) ? (v0.x + 1.f) : expf(v0.x);
                v0.y = (v0.y > 0.f) ? (v0.y + 1.f) : expf(v0.y);
                v1.x = (v1.x > 0.f) ? (v1.x + 1.f) : expf(v1.x);
                v1.y = (v1.y > 0.f) ? (v1.y + 1.f) : expf(v1.y);
            }
            if (F16OUT) {
                __half* Y = (__half*)Yv;
                *(__half2*)&Y[(size_t)m1 * EE + n0 + nn]       = __floats2half2_rn(v0.x, v0.y);
                *(__half2*)&Y[(size_t)(m1 + 8) * EE + n0 + nn] = __floats2half2_rn(v1.x, v1.y);
            } else {
                float* Y = (float*)Yv;
                *(float2*)&Y[(size_t)m1 * EE + n0 + nn] = v0;
                *(float2*)&Y[(size_t)(m1 + 8) * EE + n0 + nn] = v1;
            }
        }
    }
}

// ---------------- Pass A: Mc = K^T V + z via mma --------------------------------
__global__ __launch_bounds__(256) void chunk_sums_kernel()
{
    int blk = blockIdx.x;
    int bh = blk / NCH, c = blk % NCH;
    int b = bh / HH, h = bh % HH;

    extern __shared__ __half sh[];
    __half* KT = sh;
    __half* VT = sh + 64 * 136;
    int tid = threadIdx.x;
    size_t base = ((size_t)b * TT + (size_t)c * CHUNK) * EE + h * DD;

    for (int i = tid; i < 128 * 32; i += 256) {
        int e2 = i & 31, t = i >> 5;
        __half2 kv = *(const __half2*)&g_kf[base + (size_t)t * EE + e2 * 2];
        __half2 vv = *(const __half2*)&g_vf[base + (size_t)t * EE + e2 * 2];
        KT[(2*e2) * 136 + t] = __low2half(kv);  KT[(2*e2+1) * 136 + t] = __high2half(kv);
        VT[(2*e2) * 136 + t] = __low2half(vv);  VT[(2*e2+1) * 136 + t] = __high2half(vv);
    }
    __syncthreads();

    uint32_t sb = smem_u32(sh);
    int lid = tid & 31, wid = tid >> 5;
    int wm = (wid & 1) * 32, wn = (wid >> 1) * 16;
    float acc[2][2][4];
#pragma unroll
    for (int mi = 0; mi < 2; mi++)
#pragma unroll
        for (int ni = 0; ni < 2; ni++)
#pragma unroll
            for (int kk = 0; kk < 4; kk++) acc[mi][ni][kk] = 0.f;

    const int arow = lid & 15, acol = (lid >> 4) << 3;
    const int brow = lid & 7,  bcol = lid & 8;

#pragma unroll
    for (int kt = 0; kt < 8; kt++) {
        int k0 = kt * 16;
        uint32_t ar[2][4], br[2][2];
#pragma unroll
        for (int mi = 0; mi < 2; mi++)
            ldsm_x4(ar[mi], sb + ((wm + mi*16 + arow) * 136 + k0 + acol) * 2);
#pragma unroll
        for (int ni = 0; ni < 2; ni++)
            ldsm_x2(br[ni], sb + (64*136 + (wn + ni*8 + brow) * 136 + k0 + bcol) * 2);
#pragma unroll
        for (int mi = 0; mi < 2; mi++)
#pragma unroll
            for (int ni = 0; ni < 2; ni++)
                mma_f16(acc[mi][ni], ar[mi], br[ni]);
    }

    int er = lid >> 2, ec = (lid & 3) * 2;
    float* Mout = g_Mc + (size_t)blk * DD * DD;
#pragma unroll
    for (int mi = 0; mi < 2; mi++)
#pragma unroll
        for (int ni = 0; ni < 2; ni++) {
            int d = wm + mi * 16 + er, e = wn + ni * 8 + ec;
            *(float2*)&Mout[d * DD + e]       = make_float2(acc[mi][ni][0], acc[mi][ni][1]);
            *(float2*)&Mout[(d + 8) * DD + e] = make_float2(acc[mi][ni][2], acc[mi][ni][3]);
        }

    if (tid < DD) {
        float zz = 0.f;
        const __half2* row = (const __half2*)&KT[tid * 136];
#pragma unroll 8
        for (int t2 = 0; t2 < 64; t2++) {
            float2 f = __half22float2(row[t2]);
            zz += f.x + f.y;
        }
        g_zc[(size_t)blk * DD + tid] = zz;
    }
}

// ---------------- Pass B: exclusive prefix, 8-wide load batching ----------------
__global__ void prefix_kernel()
{
    int idx = blockIdx.x * 256 + threadIdx.x;
    const int PER = DD * DD + DD;
    if (idx >= NBH * PER) return;
    int bh = idx / PER;
    int r  = idx % PER;
    if (r < DD * DD) {
        float run = 0.f;
#pragma unroll
        for (int cb = 0; cb < NCH; cb += 8) {
            float v[8];
#pragma unroll
            for (int j = 0; j < 8; j++)
                v[j] = g_Mc[(size_t)(bh * NCH + cb + j) * DD * DD + r];
#pragma unroll
            for (int j = 0; j < 8; j++) {
                g_Mp[(size_t)(bh * NCH + cb + j) * DD * DD + r] = run;
                run += v[j];
            }
        }
    } else {
        int d = r - DD * DD;
        float run = 0.f;
#pragma unroll
        for (int cb = 0; cb < NCH; cb += 8) {
            float v[8];
#pragma unroll
            for (int j = 0; j < 8; j++)
                v[j] = g_zc[(size_t)(bh * NCH + cb + j) * DD + d];
#pragma unroll
            for (int j = 0; j < 8; j++) {
                g_zp[(size_t)(bh * NCH + cb + j) * DD + d] = run;
                run += v[j];
            }
        }
    }
}

// ---------------- Pass C: tensorized intra-chunk attention ----------------------
#define CA_QF 0
#define CA_KF 9216
#define CA_VT 18432
#define CA_STH 27136
#define CA_STL 31744
#define CA_A  36352
#define CA_ZB 107520
#define CA_DIB 107776
#define CA_BYTES 108544

__global__ __launch_bounds__(256, 1) void chunk_attn_kernel()
{
    int blk = blockIdx.x;
    int bh = blk / NCH, c = blk % NCH;
    int b = bh / HH, h = bh % HH;

    extern __shared__ char smc[];
    __half* sh = (__half*)smc;
    float* zf  = (float*)(smc + CA_ZB);
    float* sdi = (float*)(smc + CA_DIB);
    uint32_t sb = smem_u32(smc);

    int tid = threadIdx.x, lid = tid & 31, wid = tid >> 5;
    size_t base = ((size_t)b * TT + (size_t)c * CHUNK) * EE + h * DD;
    const float* Mp = g_Mp + (size_t)blk * DD * DD;
    const float* zp = g_zp + (size_t)blk * DD;

    // q,k row-major fp16
    for (int i = tid; i < 128 * 8; i += 256) {
        int row = i >> 3, j = i & 7;
        *(uint4*)&sh[CA_QF + row * 72 + j * 8] =
            *(const uint4*)&g_qf[base + (size_t)row * EE + j * 8];
        *(uint4*)&sh[CA_KF + row * 72 + j * 8] =
            *(const uint4*)&g_kf[base + (size_t)row * EE + j * 8];
    }
    // V transposed (coalesced loads, conflicted stores — measured faster)
    for (int i = tid; i < 128 * 32; i += 256) {
        int e2 = i & 31, t = i >> 5;
        __half2 vv = *(const __half2*)&g_vf[base + (size_t)t * EE + e2 * 2];
        sh[CA_VT + (2*e2) * 136 + t] = __low2half(vv);
        sh[CA_VT + (2*e2+1) * 136 + t] = __high2half(vv);
    }
    // S^T hi/lo
    for (int i = tid; i < 64 * 16; i += 256) {
        int d = i >> 4, e4 = (i & 15) * 4;
        float4 s4 = *(const float4*)&Mp[d * DD + e4];
        float fs[4] = {s4.x, s4.y, s4.z, s4.w};
#pragma unroll
        for (int j = 0; j < 4; j++) {
            __half hi = __float2half(fs[j]);
            sh[CA_STH + (e4 + j) * 72 + d] = hi;
            sh[CA_STL + (e4 + j) * 72 + d] = __float2half(fs[j] - __half2float(hi));
        }
    }
    if (tid < DD) zf[tid] = zp[tid];
    __syncthreads();

    // ---- phase 1: A = Q K^T (causal-masked), fp16 into smem ----
    {
        int wm = (wid & 1) * 64, wn = (wid >> 1) * 32;
        const int arow = lid & 15, acol = (lid >> 4) << 3;
        const int brow = lid & 7,  bcol = lid & 8;
        float acc[4][4][4];
#pragma unroll
        for (int mi = 0; mi < 4; mi++)
#pragma unroll
            for (int ni = 0; ni < 4; ni++)
#pragma unroll
                for (int kk = 0; kk < 4; kk++) acc[mi][ni][kk] = 0.f;

        // skip warps whose whole 64x32 tile is above the diagonal (A==0 there)
        if (wn <= wm + 63) {
#pragma unroll
            for (int kt = 0; kt < 4; kt++) {
                int k0 = kt * 16;
                uint32_t ar[4][4], br[4][2];
#pragma unroll
                for (int mi = 0; mi < 4; mi++)
                    ldsm_x4(ar[mi], sb + (CA_QF + (wm + mi*16 + arow) * 72 + k0 + acol) * 2);
#pragma unroll
                for (int ni = 0; ni < 4; ni++)
                    ldsm_x2(br[ni], sb + (CA_KF + (wn + ni*8 + brow) * 72 + k0 + bcol) * 2);
#pragma unroll
                for (int mi = 0; mi < 4; mi++)
#pragma unroll
                    for (int ni = 0; ni < 4; ni++)
                        if (wn + ni * 8 <= wm + mi * 16 + 15)   // subtile touches diag
                            mma_f16(acc[mi][ni], ar[mi], br[ni]);
            }
        }

        int er = lid >> 2, ec = (lid & 3) * 2;
#pragma unroll
        for (int mi = 0; mi < 4; mi++)
#pragma unroll
            for (int ni = 0; ni < 4; ni++) {
                int t = wm + mi * 16 + er, s = wn + ni * 8 + ec;
                float c0 = (s     <= t) ? acc[mi][ni][0] : 0.f;
                float c1 = (s + 1 <= t) ? acc[mi][ni][1] : 0.f;
                int t2 = t + 8;
                float c2 = (s     <= t2) ? acc[mi][ni][2] : 0.f;
                float c3 = (s + 1 <= t2) ? acc[mi][ni][3] : 0.f;
                *(__half2*)&sh[CA_A + t  * 136 + s] = __floats2half2_rn(c0, c1);
                *(__half2*)&sh[CA_A + t2 * 136 + s] = __floats2half2_rn(c2, c3);
            }
    }
    __syncthreads();

    // ---- denominators ----
    if (tid < CHUNK) {
        int t = tid;
        float den = EPSF;
        const __half2* qr = (const __half2*)&sh[CA_QF + t * 72];
#pragma unroll 8
        for (int d2 = 0; d2 < 32; d2++) {
            float2 q = __half22float2(qr[d2]);
            den += q.x * zf[2*d2] + q.y * zf[2*d2 + 1];
        }
        const __half2* ar = (const __half2*)&sh[CA_A + t * 136];
#pragma unroll 8
        for (int s2 = 0; s2 < 64; s2++) {
            float2 a = __half22float2(ar[s2]);
            den += a.x + a.y;
        }
        sdi[t] = 1.f / den;
    }
    __syncthreads();

    // ---- phase 2: out = (A V + Q Sh + Q Sl) * inv_den -> g_af fp16 ----
    {
        int wm = (wid & 1) * 64, wn = (wid >> 1) * 16;
        const int arow = lid & 15, acol = (lid >> 4) << 3;
        const int brow = lid & 7,  bcol = lid & 8;
        float acc[4][2][4];
#pragma unroll
        for (int mi = 0; mi < 4; mi++)
#pragma unroll
            for (int ni = 0; ni < 2; ni++)
#pragma unroll
                for (int kk = 0; kk < 4; kk++) acc[mi][ni][kk] = 0.f;

        // A V  (k = s): kt tiles with k0 > wm+63 are all-zero A -> skip
        const int ktmaxAV = wm / 16 + 4;     // wm=0 -> 4, wm=64 -> 8
        for (int kt = 0; kt < ktmaxAV; kt++) {
            int k0 = kt * 16;
            uint32_t ar[4][4], br[2][2];
#pragma unroll
            for (int mi = 0; mi < 4; mi++)
                ldsm_x4(ar[mi], sb + (CA_A + (wm + mi*16 + arow) * 136 + k0 + acol) * 2);
#pragma unroll
            for (int ni = 0; ni < 2; ni++)
                ldsm_x2(br[ni], sb + (CA_VT + (wn + ni*8 + brow) * 136 + k0 + bcol) * 2);
#pragma unroll
            for (int mi = 0; mi < 4; mi++)
#pragma unroll
                for (int ni = 0; ni < 2; ni++)
                    mma_f16(acc[mi][ni], ar[mi], br[ni]);
        }
        // Q S_hi + Q S_lo  (k = d, 4 tiles each)
#pragma unroll
        for (int pass = 0; pass < 2; pass++) {
            int stoff = pass ? CA_STL : CA_STH;
#pragma unroll
            for (int kt = 0; kt < 4; kt++) {
                int k0 = kt * 16;
                uint32_t ar[4][4], br[2][2];
#pragma unroll
                for (int mi = 0; mi < 4; mi++)
                    ldsm_x4(ar[mi], sb + (CA_QF + (wm + mi*16 + arow) * 72 + k0 + acol) * 2);
#pragma unroll
                for (int ni = 0; ni < 2; ni++)
                    ldsm_x2(br[ni], sb + (stoff + (wn + ni*8 + brow) * 72 + k0 + bcol) * 2);
#pragma unroll
                for (int mi = 0; mi < 4; mi++)
#pragma unroll
                    for (int ni = 0; ni < 2; ni++)
                        mma_f16(acc[mi][ni], ar[mi], br[ni]);
            }
        }

        int er = lid >> 2, ec = (lid & 3) * 2;
#pragma unroll
        for (int mi = 0; mi < 4; mi++)
#pragma unroll
            for (int ni = 0; ni < 2; ni++) {
                int t = wm + mi * 16 + er, e = wn + ni * 8 + ec;
                float i0 = sdi[t], i1 = sdi[t + 8];
                *(__half2*)&g_af[base + (size_t)t * EE + e] =
                    __floats2half2_rn(acc[mi][ni][0] * i0, acc[mi][ni][1] * i0);
                *(__half2*)&g_af[base + (size_t)(t + 8) * EE + e] =
                    __floats2half2_rn(acc[mi][ni][2] * i1, acc[mi][ni][3] * i1);
            }
    }
}

// ---------------- host ----------------------------------------------------------
extern "C" void kernel_launch(void* const* d_in, const int* in_sizes, int n_in,
                              void* d_out, int out_size)
{
    const float* x  = (const float*)d_in[0];
    const float* Wq = (const float*)d_in[1];
    const float* bq = (const float*)d_in[2];
    const float* Wk = (const float*)d_in[3];
    const float* bk = (const float*)d_in[4];
    const float* Wv = (const float*)d_in[5];
    const float* bv = (const float*)d_in[6];
    const float* Wo = (const float*)d_in[7];
    const float* bo = (const float*)d_in[8];
    float* out = (float*)d_out;

    __half *xf, *qf, *kf, *vf, *af, *wf;
    cudaGetSymbolAddress((void**)&xf, g_xf);
    cudaGetSymbolAddress((void**)&qf, g_qf);
    cudaGetSymbolAddress((void**)&kf, g_kf);
    cudaGetSymbolAddress((void**)&vf, g_vf);
    cudaGetSymbolAddress((void**)&af, g_af);
    cudaGetSymbolAddress((void**)&wf, g_wf);

    cudaFuncSetAttribute(gemm_f16<0>, cudaFuncAttributeMaxDynamicSharedMemorySize, GSM_BYTES);
    cudaFuncSetAttribute(gemm_f16<1>, cudaFuncAttributeMaxDynamicSharedMemorySize, GSM_BYTES);
    cudaFuncSetAttribute(chunk_sums_kernel,
                         cudaFuncAttributeMaxDynamicSharedMemorySize, 2 * 64 * 136 * 2);
    cudaFuncSetAttribute(chunk_attn_kernel,
                         cudaFuncAttributeMaxDynamicSharedMemorySize, CA_BYTES);

    // fused converts: x + 4 weights in one launch
    int total4 = XN4 + 4 * WN4;
    cvt_all_kernel<<<(total4 + 255) / 256, 256>>>(x, Wq, Wk, Wv, Wo, xf, wf);

    // fused QKV projection -> fp16 q/k/v with elu+1 on q,k
    dim3 gq(MROWS / 128, 12);
    gemm_f16<1><<<gq, 256, GSM_BYTES>>>(xf, wf, bq, bk, bv, qf, kf, vf, 0x3);

    chunk_sums_kernel<<<NBH * NCH, 256, 2 * 64 * 136 * 2>>>();

    int totalPref = NBH * (DD * DD + DD);
    prefix_kernel<<<(totalPref + 255) / 256, 256>>>();

    chunk_attn_kernel<<<NBH * NCH, 256, CA_BYTES>>>();

    // output projection -> fp32 d_out
    dim3 go(MROWS / 128, 4);
    gemm_f16<0><<<go, 256, GSM_BYTES>>>(af, wf + 3*WSZ, bo, bo, bo, out, out, out, 0x0);
}